// round 15
// baseline (speedup 1.0000x reference)
#include <cuda_runtime.h>
#include <cuda_fp16.h>
#include <cstdint>
#include <cstddef>

// ---------------------------------------------------------------------------
// Problem constants
// ---------------------------------------------------------------------------
#define BSZ 2
#define NP  128
#define DIM 1024
#define GEO 64
#define TOPK 18
#define MBIG (BSZ * NP * NP)     // 32768 pairwise rows
#define MSMALL (BSZ * NP)        // 256 proposal rows
#define MN_SMALL (MSMALL * DIM)  // 262144

// ---------------------------------------------------------------------------
// Scratch (static device globals)
// ---------------------------------------------------------------------------
__device__ float g_FA[MN_SMALL];
__device__ float g_FB[MN_SMALL];
__device__ float g_SA[MN_SMALL];
__device__ unsigned short g_featsH[MN_SMALL];    // feats fp16
__device__ unsigned short g_TH[MN_SMALL];        // topk out fp16
__device__ unsigned short g_SAh[MN_SMALL];
__device__ unsigned short g_SBh[MN_SMALL];
__device__ unsigned short g_G3[MBIG * GEO];      // geo out fp16 (4 MB)
__device__ unsigned short g_H1[(size_t)MBIG * DIM];  // fp16, 64 MB
__device__ unsigned short g_H2[(size_t)MBIG * DIM];  // fp16, 64 MB
__device__ unsigned short g_W1[DIM * GEO];       // [N,K] w1 geo slice fp16
__device__ unsigned short g_W2[DIM * DIM];       // [N,K] fp16
__device__ unsigned short g_W3[DIM * DIM];       // [N,K] fp16
__device__ unsigned short g_WFA[DIM * DIM];      // pm_w1[0:1024] -> [N,K]
__device__ unsigned short g_WFB[DIM * DIM];      // pm_w1[1024:2048] -> [N,K]
__device__ unsigned short g_AG1[DIM * 2 * DIM];  // ag_w1 -> [1024, 2048]
__device__ unsigned short g_AG2[DIM * DIM];
__device__ unsigned short g_AG3[DIM * DIM];

// ---------------------------------------------------------------------------
// Helpers (sm_80+ only: cp.async, ldmatrix, mma.sync)
// ---------------------------------------------------------------------------
__device__ __forceinline__ uint32_t smem_u32(const void* p) {
    uint32_t a;
    asm("{ .reg .u64 t; cvta.to.shared.u64 t, %1; cvt.u32.u64 %0, t; }"
        : "=r"(a) : "l"(p));
    return a;
}
__device__ __forceinline__ void cp16(uint32_t dst, const void* src) {
    asm volatile("cp.async.cg.shared.global [%0], [%1], 16;" :: "r"(dst), "l"(src));
}
__device__ __forceinline__ void cp_commit() {
    asm volatile("cp.async.commit_group;" ::: "memory");
}
template<int N> __device__ __forceinline__ void cp_wait() {
    asm volatile("cp.async.wait_group %0;" :: "n"(N) : "memory");
}
#define SWZ128(o) ((o) ^ (((o) >> 3) & 0x70))

__device__ __forceinline__ void ldsm4(uint32_t& r0, uint32_t& r1,
                                      uint32_t& r2, uint32_t& r3, uint32_t addr) {
    asm volatile("ldmatrix.sync.aligned.m8n8.x4.shared.b16 {%0,%1,%2,%3}, [%4];"
                 : "=r"(r0), "=r"(r1), "=r"(r2), "=r"(r3) : "r"(addr));
}
__device__ __forceinline__ void mma_f16(float* c,
                                        const uint32_t* a, const uint32_t* b) {
    asm volatile("mma.sync.aligned.m16n8k16.row.col.f32.f16.f16.f32 "
                 "{%0,%1,%2,%3}, {%4,%5,%6,%7}, {%8,%9}, {%0,%1,%2,%3};"
                 : "+f"(c[0]), "+f"(c[1]), "+f"(c[2]), "+f"(c[3])
                 : "r"(a[0]), "r"(a[1]), "r"(a[2]), "r"(a[3]),
                   "r"(b[0]), "r"(b[1]));
}

__device__ __forceinline__ unsigned short f2h_bits(float v) {
    __half h = __float2half_rn(v);
    return *reinterpret_cast<unsigned short*>(&h);
}

// ---------------------------------------------------------------------------
// fp16 HMMA compute step over one 32 KB stage (A 16 KB + B 16 KB), warp tile
// 64x32, 8 warps 2(M)x4(N). Shared by all GEMM kernels.
// ---------------------------------------------------------------------------
#define KCH 64
#define NKC (DIM / KCH)            // 16
#define STG_BYTES 32768
#define HMMA_SMEM (3 * STG_BYTES + 128)
#define L1_SMEM (2 * 16384 + 128)

struct HmmaCtx {
    uint32_t sbase;
    int tid, lane, wm, wn, mtile, ntile;
};

__device__ __forceinline__ void hmma_compute_stage(
    const HmmaCtx& c, uint32_t s0, float acc[4][4][4])
{
    const int a_rl = c.lane & 15;
    const int a_cl = (c.lane >> 4) << 3;
    const int b_rl = (c.lane & 7) + ((c.lane >> 4) << 3);
    const int b_cl = ((c.lane >> 3) & 1) << 3;
    const uint32_t sA = s0, sB = s0 + 16384u;
#pragma unroll
    for (int ks = 0; ks < 4; ks++) {
        const int k0 = ks * 16;
        uint32_t bf[4][2];
#pragma unroll
        for (int np = 0; np < 2; np++) {
            const int n0 = c.wn * 32 + np * 16;
            const uint32_t off =
                SWZ128((uint32_t)((n0 + b_rl) * 128 + (k0 + b_cl) * 2));
            uint32_t r0, r1, r2, r3;
            ldsm4(r0, r1, r2, r3, sB + off);
            bf[np * 2][0] = r0; bf[np * 2][1] = r1;
            bf[np * 2 + 1][0] = r2; bf[np * 2 + 1][1] = r3;
        }
        uint32_t af[4][4];
#pragma unroll
        for (int mf = 0; mf < 4; mf++) {
            const int m0 = c.wm * 64 + mf * 16;
            const uint32_t off =
                SWZ128((uint32_t)((m0 + a_rl) * 128 + (k0 + a_cl) * 2));
            ldsm4(af[mf][0], af[mf][1], af[mf][2], af[mf][3], sA + off);
        }
#pragma unroll
        for (int mf = 0; mf < 4; mf++)
#pragma unroll
            for (int nf = 0; nf < 4; nf++)
                mma_f16(acc[mf][nf], af[mf], bf[nf]);
    }
}

// Big mainloop (K=1024 fixed, A/B stride DIM). Single sync per chunk.
__device__ __forceinline__ void hmma_mainloop(
    const HmmaCtx& c,
    const unsigned short* __restrict__ A,
    const unsigned short* __restrict__ B,
    float acc[4][4][4])
{
#pragma unroll
    for (int mf = 0; mf < 4; mf++)
#pragma unroll
        for (int nf = 0; nf < 4; nf++)
#pragma unroll
            for (int e = 0; e < 4; e++) acc[mf][nf][e] = 0.f;

    auto load_chunk = [&](int kc, int stg) {
        const uint32_t s0 = c.sbase + (uint32_t)stg * STG_BYTES;
#pragma unroll
        for (int it = 0; it < 4; it++) {
            int t = c.tid + (it << 8);
            int rr = t >> 3, ss = t & 7;
            cp16(s0 + SWZ128((uint32_t)(rr * 128 + ss * 16)),
                 A + (size_t)((c.mtile << 7) + rr) * DIM + kc * KCH + ss * 8);
        }
#pragma unroll
        for (int it = 0; it < 4; it++) {
            int t = c.tid + (it << 8);
            int rr = t >> 3, ss = t & 7;
            cp16(s0 + 16384u + SWZ128((uint32_t)(rr * 128 + ss * 16)),
                 B + (size_t)((c.ntile << 7) + rr) * DIM + kc * KCH + ss * 8);
        }
        cp_commit();
    };

    load_chunk(0, 0);
    load_chunk(1, 1);
    for (int kc = 0; kc < NKC; kc++) {
        if (kc + 1 < NKC) {
            cp_wait<1>();
        } else {
            cp_wait<0>();
        }
        __syncthreads();
        if (kc + 2 < NKC) load_chunk(kc + 2, (kc + 2) % 3);
        hmma_compute_stage(c, c.sbase + (uint32_t)(kc % 3) * STG_BYTES, acc);
    }
}

// Layer 2: out = relu(A @ B^T + bias) -> fp16
__global__ void __launch_bounds__(256, 2)
hmma_l2_kernel(const unsigned short* __restrict__ A,
               const unsigned short* __restrict__ B,
               const float* __restrict__ bias,
               unsigned short* __restrict__ outH)
{
    extern __shared__ char smem_raw[];
    HmmaCtx c;
    c.sbase = (smem_u32(smem_raw) + 127u) & ~127u;
    c.tid = threadIdx.x;
    c.lane = c.tid & 31;
    const int w = c.tid >> 5;
    c.wm = w >> 2; c.wn = w & 3;
    c.mtile = blockIdx.y; c.ntile = blockIdx.x;

    float acc[4][4][4];
    hmma_mainloop(c, A, B, acc);

    const int rl = c.lane >> 2;
    const int cl = (c.lane & 3) << 1;
#pragma unroll
    for (int mf = 0; mf < 4; mf++) {
        const int m_base = (c.mtile << 7) + c.wm * 64 + mf * 16 + rl;
#pragma unroll
        for (int nf = 0; nf < 4; nf++) {
            const int n = (c.ntile << 7) + c.wn * 32 + nf * 8 + cl;
            const float b0 = bias[n], b1 = bias[n + 1];
#pragma unroll
            for (int half = 0; half < 2; half++) {
                const int m = m_base + half * 8;
                float v0 = fmaxf(acc[mf][nf][half * 2 + 0] + b0, 0.f);
                float v1 = fmaxf(acc[mf][nf][half * 2 + 1] + b1, 0.f);
                *(uint32_t*)(outH + (size_t)m * DIM + n) =
                    (uint32_t)f2h_bits(v0) | ((uint32_t)f2h_bits(v1) << 16);
            }
        }
    }
}

// Layer 3 fused with top-18-sum -> fp16 T
#define TPAD 132
#define L3_LISTS (128 * TPAD * 4)

__global__ void __launch_bounds__(256, 2)
hmma_l3_topk_kernel(const unsigned short* __restrict__ A,
                    const unsigned short* __restrict__ B,
                    const float* __restrict__ bias,
                    unsigned short* __restrict__ TH)
{
    extern __shared__ char smem_raw[];
    HmmaCtx c;
    c.sbase = (smem_u32(smem_raw) + 127u) & ~127u;
    c.tid = threadIdx.x;
    c.lane = c.tid & 31;
    const int w = c.tid >> 5;
    c.wm = w >> 2; c.wn = w & 3;
    c.mtile = blockIdx.y; c.ntile = blockIdx.x;

    float acc[4][4][4];
    hmma_mainloop(c, A, B, acc);
    __syncthreads();

    char* sm_c = smem_raw + (c.sbase - smem_u32(smem_raw));
    float* smf = (float*)sm_c;
    const int rl = c.lane >> 2;
    const int cl = (c.lane & 3) << 1;
#pragma unroll
    for (int mf = 0; mf < 4; mf++) {
        const int ml_base = c.wm * 64 + mf * 16 + rl;
#pragma unroll
        for (int nf = 0; nf < 4; nf++) {
            const int nl = c.wn * 32 + nf * 8 + cl;
            const int n = (c.ntile << 7) + nl;
            const float b0 = bias[n], b1 = bias[n + 1];
#pragma unroll
            for (int half = 0; half < 2; half++) {
                const int ml = ml_base + half * 8;
                smf[ml * TPAD + nl] = acc[mf][nf][half * 2 + 0] + b0;
                smf[ml * TPAD + nl + 1] = acc[mf][nf][half * 2 + 1] + b1;
            }
        }
    }
    __syncthreads();

    const int cidx = c.tid & 127;
    const int half = c.tid >> 7;
    float t18[TOPK];
#pragma unroll
    for (int s = 0; s < TOPK; s++) t18[s] = -3.4e38f;
    const float* colp = smf + half * 64 * TPAD + cidx;
    for (int j = 0; j < 64; j++) {
        float v = colp[j * TPAD];
        if (v > t18[TOPK - 1]) {
            t18[TOPK - 1] = v;
#pragma unroll
            for (int s = TOPK - 1; s > 0; s--) {
                if (t18[s] > t18[s - 1]) {
                    float tmp = t18[s - 1]; t18[s - 1] = t18[s]; t18[s] = tmp;
                }
            }
        }
    }
    float* lists = (float*)(sm_c + L3_LISTS);
    if (half == 1) {
#pragma unroll
        for (int s = 0; s < TOPK; s++) lists[cidx * TOPK + s] = t18[s];
    }
    __syncthreads();
    if (half == 0) {
#pragma unroll
        for (int s = 0; s < TOPK; s++) {
            float v = lists[cidx * TOPK + s];
            if (v > t18[TOPK - 1]) {
                t18[TOPK - 1] = v;
#pragma unroll
                for (int q = TOPK - 1; q > 0; q--) {
                    if (t18[q] > t18[q - 1]) {
                        float tmp = t18[q - 1]; t18[q - 1] = t18[q]; t18[q] = tmp;
                    }
                }
            }
        }
        float sum = 0.f;
#pragma unroll
        for (int s = 0; s < TOPK; s++) sum += t18[s];
        TH[(size_t)c.mtile * DIM + (c.ntile << 7) + cidx] =
            f2h_bits(sum * 0.125f);
    }
}

// ---------------------------------------------------------------------------
// Layer-1 fp16 HMMA (K=64): H1 = relu( G3 @ W1g^T + FA_j + FB_i + b1 )
// ---------------------------------------------------------------------------
__global__ void __launch_bounds__(256, 3)
hmma_l1_kernel(const unsigned short* __restrict__ A,
               const unsigned short* __restrict__ B,
               const float* __restrict__ bias,
               const float* __restrict__ FA,
               const float* __restrict__ FB,
               unsigned short* __restrict__ outH)
{
    extern __shared__ char smem_raw[];
    HmmaCtx c;
    c.sbase = (smem_u32(smem_raw) + 127u) & ~127u;
    c.tid = threadIdx.x;
    c.lane = c.tid & 31;
    const int w = c.tid >> 5;
    c.wm = w >> 2; c.wn = w & 3;
    c.mtile = blockIdx.y; c.ntile = blockIdx.x;

    // load A[128x64], B[128x64] (stride GEO)
#pragma unroll
    for (int it = 0; it < 4; it++) {
        int t = c.tid + (it << 8);
        int rr = t >> 3, ss = t & 7;
        cp16(c.sbase + SWZ128((uint32_t)(rr * 128 + ss * 16)),
             A + (size_t)((c.mtile << 7) + rr) * GEO + ss * 8);
    }
#pragma unroll
    for (int it = 0; it < 4; it++) {
        int t = c.tid + (it << 8);
        int rr = t >> 3, ss = t & 7;
        cp16(c.sbase + 16384u + SWZ128((uint32_t)(rr * 128 + ss * 16)),
             B + (size_t)((c.ntile << 7) + rr) * GEO + ss * 8);
    }
    cp_commit();

    float acc[4][4][4];
#pragma unroll
    for (int mf = 0; mf < 4; mf++)
#pragma unroll
        for (int nf = 0; nf < 4; nf++)
#pragma unroll
            for (int e = 0; e < 4; e++) acc[mf][nf][e] = 0.f;

    cp_wait<0>();
    __syncthreads();
    hmma_compute_stage(c, c.sbase, acc);

    const int rl = c.lane >> 2;
    const int cl = (c.lane & 3) << 1;
#pragma unroll
    for (int mf = 0; mf < 4; mf++) {
        const int m_base = (c.mtile << 7) + c.wm * 64 + mf * 16 + rl;
#pragma unroll
        for (int nf = 0; nf < 4; nf++) {
            const int n = (c.ntile << 7) + c.wn * 32 + nf * 8 + cl;
            const float b0 = bias[n], b1 = bias[n + 1];
#pragma unroll
            for (int half = 0; half < 2; half++) {
                const int m = m_base + half * 8;
                const int j = m & (NP - 1);
                const int bi = m >> 7;
                const int bb = bi >> 7;
                const float* aJ = FA + (size_t)((bb << 7) + j) * DIM;
                const float* aI = FB + (size_t)bi * DIM;
                float v0 = acc[mf][nf][half * 2 + 0] + b0 + aJ[n] + aI[n];
                float v1 = acc[mf][nf][half * 2 + 1] + b1 + aJ[n + 1] + aI[n + 1];
                v0 = fmaxf(v0, 0.f); v1 = fmaxf(v1, 0.f);
                *(uint32_t*)(outH + (size_t)m * DIM + n) =
                    (uint32_t)f2h_bits(v0) | ((uint32_t)f2h_bits(v1) << 16);
            }
        }
    }
}

// ---------------------------------------------------------------------------
// Full-K small GEMM (M=256): out = act( [A0|A1] @ B_z^T + bias ).
// A0 holds nca0 K-chunks, A1 (optional) the rest; both row stride DIM.
// B row stride KB. z (gridDim.z) selects (B0,out0) or (B1,out1).
// Fused epilogue: optional bias/relu, fp32 or fp16 output (N = DIM).
// 3-stage cp.async pipeline; few CTAs but latency-covered.
// ---------------------------------------------------------------------------
__global__ void __launch_bounds__(256, 2)
hmma_small_kernel(const unsigned short* __restrict__ A0,
                  const unsigned short* __restrict__ A1, int nca0, int nkctot,
                  const unsigned short* __restrict__ B0,
                  const unsigned short* __restrict__ B1, int KB,
                  const float* __restrict__ bias, int relu,
                  float* __restrict__ outF0, float* __restrict__ outF1,
                  unsigned short* __restrict__ outH)
{
    extern __shared__ char smem_raw[];
    HmmaCtx c;
    c.sbase = (smem_u32(smem_raw) + 127u) & ~127u;
    c.tid = threadIdx.x;
    c.lane = c.tid & 31;
    const int w = c.tid >> 5;
    c.wm = w >> 2; c.wn = w & 3;
    c.mtile = blockIdx.y; c.ntile = blockIdx.x;
    const int z = blockIdx.z;

    const unsigned short* B = (z == 0) ? B0 : B1;
    float* outF = (z == 0) ? outF0 : outF1;

    float acc[4][4][4];
#pragma unroll
    for (int mf = 0; mf < 4; mf++)
#pragma unroll
        for (int nf = 0; nf < 4; nf++)
#pragma unroll
            for (int e = 0; e < 4; e++) acc[mf][nf][e] = 0.f;

    auto load_chunk = [&](int kc, int stg) {
        const uint32_t s0 = c.sbase + (uint32_t)stg * STG_BYTES;
        const unsigned short* Asrc = (kc < nca0) ? A0 : A1;
        const int akc = (kc < nca0) ? kc : kc - nca0;
#pragma unroll
        for (int it = 0; it < 4; it++) {
            int t = c.tid + (it << 8);
            int rr = t >> 3, ss = t & 7;
            cp16(s0 + SWZ128((uint32_t)(rr * 128 + ss * 16)),
                 Asrc + (size_t)((c.mtile << 7) + rr) * DIM + akc * KCH + ss * 8);
        }
#pragma unroll
        for (int it = 0; it < 4; it++) {
            int t = c.tid + (it << 8);
            int rr = t >> 3, ss = t & 7;
            cp16(s0 + 16384u + SWZ128((uint32_t)(rr * 128 + ss * 16)),
                 B + (size_t)((c.ntile << 7) + rr) * KB + kc * KCH + ss * 8);
        }
        cp_commit();
    };

    load_chunk(0, 0);
    load_chunk(1, 1);
    for (int kc = 0; kc < nkctot; kc++) {
        if (kc + 1 < nkctot) {
            cp_wait<1>();
        } else {
            cp_wait<0>();
        }
        __syncthreads();
        if (kc + 2 < nkctot) load_chunk(kc + 2, (kc + 2) % 3);
        hmma_compute_stage(c, c.sbase + (uint32_t)(kc % 3) * STG_BYTES, acc);
    }

    const int rl = c.lane >> 2;
    const int cl = (c.lane & 3) << 1;
#pragma unroll
    for (int mf = 0; mf < 4; mf++) {
        const int m_base = (c.mtile << 7) + c.wm * 64 + mf * 16 + rl;
#pragma unroll
        for (int nf = 0; nf < 4; nf++) {
            const int n = (c.ntile << 7) + c.wn * 32 + nf * 8 + cl;
            float b0 = 0.f, b1 = 0.f;
            if (bias) { b0 = bias[n]; b1 = bias[n + 1]; }
#pragma unroll
            for (int half = 0; half < 2; half++) {
                const int m = m_base + half * 8;
                float v0 = acc[mf][nf][half * 2 + 0] + b0;
                float v1 = acc[mf][nf][half * 2 + 1] + b1;
                if (relu) { v0 = fmaxf(v0, 0.f); v1 = fmaxf(v1, 0.f); }
                if (outH) {
                    *(uint32_t*)(outH + (size_t)m * DIM + n) =
                        (uint32_t)f2h_bits(v0) | ((uint32_t)f2h_bits(v1) << 16);
                } else {
                    float2 v; v.x = v0; v.y = v1;
                    *(float2*)(outF + (size_t)m * DIM + n) = v;
                }
            }
        }
    }
}

// ---------------------------------------------------------------------------
// Weight transpose + fp16 convert:  W[Kd, Nd] -> Wh [Nd, Kd]
// ---------------------------------------------------------------------------
__global__ void wsplit_kernel(const float* __restrict__ W,
                              unsigned short* __restrict__ Wh,
                              int Kd, int Nd)
{
    __shared__ float tile[32][33];
    const int n0 = blockIdx.x * 32, k0 = blockIdx.y * 32;
    const int tx = threadIdx.x, ty = threadIdx.y;   // 32 x 8
#pragma unroll
    for (int i = 0; i < 32; i += 8)
        tile[ty + i][tx] = W[(size_t)(k0 + ty + i) * Nd + n0 + tx];
    __syncthreads();
#pragma unroll
    for (int i = 0; i < 32; i += 8) {
        Wh[(size_t)(n0 + ty + i) * Kd + k0 + tx] = f2h_bits(tile[tx][ty + i]);
    }
}

// fp32 -> fp16 elementwise
__global__ void h_convert_kernel(const float* __restrict__ X,
                                 unsigned short* __restrict__ Xh, int n)
{
    int idx = blockIdx.x * blockDim.x + threadIdx.x;
    if (idx < n) Xh[idx] = f2h_bits(X[idx]);
}

// ---------------------------------------------------------------------------
// Geo embedding + 3-layer 64-wide MLP (fused) -> fp16 output
// ---------------------------------------------------------------------------
__global__ __launch_bounds__(128)
void geo_kernel(const float* __restrict__ prop,
                const float* __restrict__ w1, const float* __restrict__ b1,
                const float* __restrict__ w2, const float* __restrict__ b2,
                const float* __restrict__ w3, const float* __restrict__ b3,
                unsigned short* __restrict__ G3)
{
    __shared__ float sw1[GEO * GEO], sw2[GEO * GEO], sw3[GEO * GEO];
    __shared__ float sb1[GEO], sb2[GEO], sb3[GEO];
    __shared__ float esm[128 * 65];

    const int tid = threadIdx.x;
    for (int t = tid; t < GEO * GEO; t += blockDim.x) {
        sw1[t] = w1[t]; sw2[t] = w2[t]; sw3[t] = w3[t];
    }
    for (int t = tid; t < GEO; t += blockDim.x) {
        sb1[t] = b1[t]; sb2[t] = b2[t]; sb3[t] = b3[t];
    }
    __syncthreads();

    const int row = blockIdx.x * blockDim.x + tid;
    const int b = row >> 14;
    const int i = (row >> 7) & (NP - 1);
    const int j = row & (NP - 1);

    const float* pi = prop + ((size_t)(b * NP + i)) * 4;
    const float* pj = prop + ((size_t)(b * NP + j)) * 4;
    float wi = pi[2] - pi[0] + 1.f, hi = pi[3] - pi[1] + 1.f;
    float wj = pj[2] - pj[0] + 1.f, hj = pj[3] - pj[1] + 1.f;
    float cxi = 0.5f * (pi[0] + pi[2]), cyi = 0.5f * (pi[1] + pi[3]);
    float cxj = 0.5f * (pj[0] + pj[2]), cyj = 0.5f * (pj[1] + pj[3]);

    float pos[4];
    pos[0] = (cxi - cxj) / wj;
    pos[1] = (cyi - cyj) / hj;
    pos[2] = wi / wj;
    pos[3] = hi / hj;

    const float dm[8] = {1.0f, 2.3713737f, 5.6234133f, 13.335215f,
                         31.622777f, 74.989421f, 177.82794f, 421.69650f};

    float* my = &esm[tid * 65];
#pragma unroll
    for (int p = 0; p < 4; p++) {
        float lp = logf(fmaxf(fabsf(pos[p]), 1e-3f)) * 100.f;
#pragma unroll
        for (int r = 0; r < 8; r++) {
            float arg = lp / dm[r];
            float s, cc;
            sincosf(arg, &s, &cc);
            my[p * 16 + r] = s;
            my[p * 16 + 8 + r] = cc;
        }
    }

    float acc[GEO];
#pragma unroll
    for (int o = 0; o < GEO; o++) acc[o] = sb1[o];
    for (int k = 0; k < GEO; k++) {
        float ek = my[k];
        const float* wr = &sw1[k * GEO];
#pragma unroll
        for (int o = 0; o < GEO; o++) acc[o] = fmaf(ek, wr[o], acc[o]);
    }
#pragma unroll
    for (int o = 0; o < GEO; o++) my[o] = fmaxf(acc[o], 0.f);

#pragma unroll
    for (int o = 0; o < GEO; o++) acc[o] = sb2[o];
    for (int k = 0; k < GEO; k++) {
        float ek = my[k];
        const float* wr = &sw2[k * GEO];
#pragma unroll
        for (int o = 0; o < GEO; o++) acc[o] = fmaf(ek, wr[o], acc[o]);
    }
#pragma unroll
    for (int o = 0; o < GEO; o++) my[o] = fmaxf(acc[o], 0.f);

#pragma unroll
    for (int o = 0; o < GEO; o++) acc[o] = sb3[o];
    for (int k = 0; k < GEO; k++) {
        float ek = my[k];
        const float* wr = &sw3[k * GEO];
#pragma unroll
        for (int o = 0; o < GEO; o++) acc[o] = fmaf(ek, wr[o], acc[o]);
    }
    unsigned short* outp = G3 + (size_t)row * GEO;
#pragma unroll
    for (int o = 0; o < GEO; o++) outp[o] = f2h_bits(acc[o]);
}

// ---------------------------------------------------------------------------
// heads
// ---------------------------------------------------------------------------
__global__ __launch_bounds__(128)
void heads_kernel(const float* __restrict__ X,
                  const float* __restrict__ subject,
                  const float* __restrict__ obj,
                  const float* __restrict__ cs_w, const float* __restrict__ cs_b,
                  const float* __restrict__ cso_w, const float* __restrict__ cso_b,
                  float* __restrict__ out)
{
    int row = blockIdx.x;
    int b = row >> 7;
    int tid = threadIdx.x;

    float as = 0.f, ao = 0.f;
    for (int k = tid; k < DIM; k += 128) {
        float xv = X[(size_t)row * DIM + k];
        float sv = subject[(size_t)b * DIM + k];
        float ov = obj[(size_t)b * DIM + k];
        as += xv * cs_w[k] + sv * cs_w[DIM + k];
        ao += xv * cso_w[k] + ov * cso_w[DIM + k];
    }
    __shared__ float rs[128], ro[128];
    rs[tid] = as; ro[tid] = ao;
    __syncthreads();
    for (int s = 64; s > 0; s >>= 1) {
        if (tid < s) { rs[tid] += rs[tid + s]; ro[tid] += ro[tid + s]; }
        __syncthreads();
    }
    if (tid == 0) {
        float s1 = rs[0] + cs_b[0];
        float s2 = ro[0] + cso_b[0];
        out[row * 2 + 0] = 1.f / (1.f + expf(-s1));
        out[row * 2 + 1] = 1.f / (1.f + expf(-s2));
    }
}

// ---------------------------------------------------------------------------
// Launch (forked: geo first on side stream; W2/W3 + AG converts overlap l1+)
// ---------------------------------------------------------------------------
extern "C" void kernel_launch(void* const* d_in, const int* in_sizes, int n_in,
                              void* d_out, int out_size)
{
    const float* feats   = (const float*)d_in[0];
    const float* subject = (const float*)d_in[1];
    const float* obj     = (const float*)d_in[2];
    const float* prop    = (const float*)d_in[3];
    const float* gp_w1 = (const float*)d_in[4];
    const float* gp_b1 = (const float*)d_in[5];
    const float* gp_w2 = (const float*)d_in[6];
    const float* gp_b2 = (const float*)d_in[7];
    const float* gp_w3 = (const float*)d_in[8];
    const float* gp_b3 = (const float*)d_in[9];
    const float* pm_w1 = (const float*)d_in[10];
    const float* pm_b1 = (const float*)d_in[11];
    const float* pm_w2 = (const float*)d_in[12];
    const float* pm_b2 = (const float*)d_in[13];
    const float* pm_w3 = (const float*)d_in[14];
    const float* pm_b3 = (const float*)d_in[15];
    const float* ag_w1 = (const float*)d_in[16];
    const float* ag_b1 = (const float*)d_in[17];
    const float* ag_w2 = (const float*)d_in[18];
    const float* ag_b2 = (const float*)d_in[19];
    const float* ag_w3 = (const float*)d_in[20];
    const float* ag_b3 = (const float*)d_in[21];
    const float* cs_w  = (const float*)d_in[22];
    const float* cs_b  = (const float*)d_in[23];
    const float* cso_w = (const float*)d_in[24];
    const float* cso_b = (const float*)d_in[25];
    float* out = (float*)d_out;

    float *FA, *FB, *SA;
    unsigned short *featsH, *TH, *SAh, *SBh;
    unsigned short *G3, *H1, *H2, *W1, *W2, *W3, *WFA, *WFB, *AG1, *AG2, *AG3;
    cudaGetSymbolAddress((void**)&FA, g_FA);
    cudaGetSymbolAddress((void**)&FB, g_FB);
    cudaGetSymbolAddress((void**)&SA, g_SA);
    cudaGetSymbolAddress((void**)&featsH, g_featsH);
    cudaGetSymbolAddress((void**)&TH, g_TH);
    cudaGetSymbolAddress((void**)&SAh, g_SAh);
    cudaGetSymbolAddress((void**)&SBh, g_SBh);
    cudaGetSymbolAddress((void**)&G3, g_G3);
    cudaGetSymbolAddress((void**)&H1, g_H1);
    cudaGetSymbolAddress((void**)&H2, g_H2);
    cudaGetSymbolAddress((void**)&W1, g_W1);
    cudaGetSymbolAddress((void**)&W2, g_W2);
    cudaGetSymbolAddress((void**)&W3, g_W3);
    cudaGetSymbolAddress((void**)&WFA, g_WFA);
    cudaGetSymbolAddress((void**)&WFB, g_WFB);
    cudaGetSymbolAddress((void**)&AG1, g_AG1);
    cudaGetSymbolAddress((void**)&AG2, g_AG2);
    cudaGetSymbolAddress((void**)&AG3, g_AG3);

    cudaFuncSetAttribute(hmma_l2_kernel,
                         cudaFuncAttributeMaxDynamicSharedMemorySize, HMMA_SMEM);
    cudaFuncSetAttribute(hmma_l3_topk_kernel,
                         cudaFuncAttributeMaxDynamicSharedMemorySize, HMMA_SMEM);
    cudaFuncSetAttribute(hmma_l1_kernel,
                         cudaFuncAttributeMaxDynamicSharedMemorySize, L1_SMEM);
    cudaFuncSetAttribute(hmma_small_kernel,
                         cudaFuncAttributeMaxDynamicSharedMemorySize, HMMA_SMEM);

    dim3 ghm(DIM / 128, MBIG / 128);          // (8, 256)
    dim3 gws(DIM / 32, DIM / 32);
    dim3 gws1(DIM / 32, GEO / 32);
    const int MN = MN_SMALL;

    // ---- forked prologue ----
    cudaStream_t s1;
    cudaEvent_t eFork, eJoin, eJoin2, eJoin3;
    bool forked =
        (cudaStreamCreateWithFlags(&s1, cudaStreamNonBlocking) == cudaSuccess) &&
        (cudaEventCreateWithFlags(&eFork, cudaEventDisableTiming) == cudaSuccess) &&
        (cudaEventCreateWithFlags(&eJoin, cudaEventDisableTiming) == cudaSuccess) &&
        (cudaEventCreateWithFlags(&eJoin2, cudaEventDisableTiming) == cudaSuccess) &&
        (cudaEventCreateWithFlags(&eJoin3, cudaEventDisableTiming) == cudaSuccess);

    if (forked) forked = (cudaEventRecord(eFork, 0) == cudaSuccess) &&
                         (cudaStreamWaitEvent(s1, eFork, 0) == cudaSuccess);

    cudaStream_t sb = forked ? s1 : 0;

    // branch B: geo first (l1 dep), then W2/W3 (l2/l3 dep), then AG converts
    geo_kernel<<<MBIG / 128, 128, 0, sb>>>(prop, gp_w1, gp_b1, gp_w2, gp_b2,
                                           gp_w3, gp_b3, G3);
    if (forked) cudaEventRecord(eJoin, s1);
    wsplit_kernel<<<gws, dim3(32, 8), 0, sb>>>(pm_w2, W2, DIM, DIM);
    wsplit_kernel<<<gws, dim3(32, 8), 0, sb>>>(pm_w3, W3, DIM, DIM);
    if (forked) cudaEventRecord(eJoin2, s1);
    wsplit_kernel<<<dim3(DIM / 32, 2 * DIM / 32), dim3(32, 8), 0, sb>>>(
        ag_w1, AG1, 2 * DIM, DIM);
    wsplit_kernel<<<gws, dim3(32, 8), 0, sb>>>(ag_w2, AG2, DIM, DIM);
    wsplit_kernel<<<gws, dim3(32, 8), 0, sb>>>(ag_w3, AG3, DIM, DIM);
    if (forked) cudaEventRecord(eJoin3, s1);

    // main branch: converts + FA/FB full-K HMMA (fused, no partials)
    h_convert_kernel<<<MN / 256, 256>>>(feats, featsH, MN);
    wsplit_kernel<<<gws1, dim3(32, 8)>>>(pm_w1 + (size_t)2 * DIM * DIM,
                                         W1, GEO, DIM);
    wsplit_kernel<<<gws, dim3(32, 8)>>>(pm_w1, WFA, DIM, DIM);
    wsplit_kernel<<<gws, dim3(32, 8)>>>(pm_w1 + (size_t)DIM * DIM, WFB, DIM, DIM);
    dim3 gsm2(DIM / 128, MSMALL / 128, 2);    // (8, 2, 2)
    hmma_small_kernel<<<gsm2, 256, HMMA_SMEM>>>(
        featsH, nullptr, NKC, NKC, WFA, WFB, DIM,
        nullptr, 0, FA, FB, nullptr);

    if (forked) cudaStreamWaitEvent(0, eJoin, 0);

    // Pairwise layer 1 (fp16 HMMA, K=64) -> H1 fp16
    hmma_l1_kernel<<<ghm, 256, L1_SMEM>>>(G3, W1, pm_b1, FA, FB, H1);

    if (forked) cudaStreamWaitEvent(0, eJoin2, 0);

    // Pairwise layer 2 (fp16 HMMA) -> H2 fp16, relu
    hmma_l2_kernel<<<ghm, 256, HMMA_SMEM>>>(H1, W2, pm_b2, H2);
    // Pairwise layer 3 + fused top-18 sum -> TH fp16
    hmma_l3_topk_kernel<<<ghm, 256, HMMA_SMEM>>>(H2, W3, pm_b3, TH);

    if (forked) cudaStreamWaitEvent(0, eJoin3, 0);

    // Aggregate MLP: full-K HMMA, fused bias/relu, no partials
    dim3 gsm1(DIM / 128, MSMALL / 128, 1);    // (8, 2, 1)
    hmma_small_kernel<<<gsm1, 256, HMMA_SMEM>>>(
        featsH, TH, NKC, 2 * NKC, AG1, nullptr, 2 * DIM,
        ag_b1, 1, nullptr, nullptr, SAh);
    hmma_small_kernel<<<gsm1, 256, HMMA_SMEM>>>(
        SAh, nullptr, NKC, NKC, AG2, nullptr, DIM,
        ag_b2, 1, nullptr, nullptr, SBh);
    hmma_small_kernel<<<gsm1, 256, HMMA_SMEM>>>(
        SBh, nullptr, NKC, NKC, AG3, nullptr, DIM,
        ag_b3, 0, SA, nullptr, nullptr);

    // Heads
    heads_kernel<<<MSMALL, 128>>>(SA, subject, obj, cs_w, cs_b, cso_w, cso_b, out);
}

// round 16
// speedup vs baseline: 1.0430x; 1.0430x over previous
#include <cuda_runtime.h>
#include <cuda_fp16.h>
#include <cstdint>
#include <cstddef>

// ---------------------------------------------------------------------------
// Problem constants
// ---------------------------------------------------------------------------
#define BSZ 2
#define NP  128
#define DIM 1024
#define GEO 64
#define TOPK 18
#define MBIG (BSZ * NP * NP)     // 32768 pairwise rows
#define MSMALL (BSZ * NP)        // 256 proposal rows
#define MN_SMALL (MSMALL * DIM)  // 262144

// ---------------------------------------------------------------------------
// Scratch (static device globals)
// ---------------------------------------------------------------------------
__device__ float g_FA[MN_SMALL];
__device__ float g_FB[MN_SMALL];
__device__ float g_SA[MN_SMALL];
__device__ float g_P[32 * MN_SMALL];             // split-K partials (32 MB)
__device__ unsigned short g_featsH[MN_SMALL];    // feats fp16
__device__ unsigned short g_TH[MN_SMALL];        // topk out fp16
__device__ unsigned short g_SAh[MN_SMALL];
__device__ unsigned short g_SBh[MN_SMALL];
__device__ unsigned short g_G3[MBIG * GEO];      // geo out fp16 (4 MB)
__device__ unsigned short g_H1[(size_t)MBIG * DIM];  // fp16, 64 MB
__device__ unsigned short g_H2[(size_t)MBIG * DIM];  // fp16, 64 MB
__device__ unsigned short g_W1[DIM * GEO];       // [N,K] w1 geo slice fp16
__device__ unsigned short g_W2[DIM * DIM];       // [N,K] fp16
__device__ unsigned short g_W3[DIM * DIM];       // [N,K] fp16
__device__ unsigned short g_WFA[DIM * DIM];      // pm_w1[0:1024] -> [N,K]
__device__ unsigned short g_WFB[DIM * DIM];      // pm_w1[1024:2048] -> [N,K]
__device__ unsigned short g_AG1[DIM * 2 * DIM];  // ag_w1 -> [1024, 2048]
__device__ unsigned short g_AG2[DIM * DIM];
__device__ unsigned short g_AG3[DIM * DIM];

// ---------------------------------------------------------------------------
// Helpers (sm_80+ only: cp.async, ldmatrix, mma.sync)
// ---------------------------------------------------------------------------
__device__ __forceinline__ uint32_t smem_u32(const void* p) {
    uint32_t a;
    asm("{ .reg .u64 t; cvta.to.shared.u64 t, %1; cvt.u32.u64 %0, t; }"
        : "=r"(a) : "l"(p));
    return a;
}
__device__ __forceinline__ void cp16(uint32_t dst, const void* src) {
    asm volatile("cp.async.cg.shared.global [%0], [%1], 16;" :: "r"(dst), "l"(src));
}
__device__ __forceinline__ void cp_commit() {
    asm volatile("cp.async.commit_group;" ::: "memory");
}
template<int N> __device__ __forceinline__ void cp_wait() {
    asm volatile("cp.async.wait_group %0;" :: "n"(N) : "memory");
}
#define SWZ128(o) ((o) ^ (((o) >> 3) & 0x70))

__device__ __forceinline__ void ldsm4(uint32_t& r0, uint32_t& r1,
                                      uint32_t& r2, uint32_t& r3, uint32_t addr) {
    asm volatile("ldmatrix.sync.aligned.m8n8.x4.shared.b16 {%0,%1,%2,%3}, [%4];"
                 : "=r"(r0), "=r"(r1), "=r"(r2), "=r"(r3) : "r"(addr));
}
__device__ __forceinline__ void mma_f16(float* c,
                                        const uint32_t* a, const uint32_t* b) {
    asm volatile("mma.sync.aligned.m16n8k16.row.col.f32.f16.f16.f32 "
                 "{%0,%1,%2,%3}, {%4,%5,%6,%7}, {%8,%9}, {%0,%1,%2,%3};"
                 : "+f"(c[0]), "+f"(c[1]), "+f"(c[2]), "+f"(c[3])
                 : "r"(a[0]), "r"(a[1]), "r"(a[2]), "r"(a[3]),
                   "r"(b[0]), "r"(b[1]));
}

__device__ __forceinline__ unsigned short f2h_bits(float v) {
    __half h = __float2half_rn(v);
    return *reinterpret_cast<unsigned short*>(&h);
}

// ---------------------------------------------------------------------------
// fp16 HMMA mainloop (128x128 CTA tile; 8 warps 2(M)x4(N); warp tile 64x32).
// Single __syncthreads per k-chunk.
// ---------------------------------------------------------------------------
#define KCH 64
#define NKC (DIM / KCH)            // 16
#define STG_BYTES 32768
#define HMMA_SMEM (3 * STG_BYTES + 128)
#define L1_SMEM (2 * 16384 + 128)

struct HmmaCtx {
    uint32_t sbase;
    int tid, lane, wm, wn, mtile, ntile;
};

__device__ __forceinline__ void hmma_compute_stage(
    const HmmaCtx& c, uint32_t s0, float acc[4][4][4])
{
    const int a_rl = c.lane & 15;
    const int a_cl = (c.lane >> 4) << 3;
    const int b_rl = (c.lane & 7) + ((c.lane >> 4) << 3);
    const int b_cl = ((c.lane >> 3) & 1) << 3;
    const uint32_t sA = s0, sB = s0 + 16384u;
#pragma unroll
    for (int ks = 0; ks < 4; ks++) {
        const int k0 = ks * 16;
        uint32_t bf[4][2];
#pragma unroll
        for (int np = 0; np < 2; np++) {
            const int n0 = c.wn * 32 + np * 16;
            const uint32_t off =
                SWZ128((uint32_t)((n0 + b_rl) * 128 + (k0 + b_cl) * 2));
            uint32_t r0, r1, r2, r3;
            ldsm4(r0, r1, r2, r3, sB + off);
            bf[np * 2][0] = r0; bf[np * 2][1] = r1;
            bf[np * 2 + 1][0] = r2; bf[np * 2 + 1][1] = r3;
        }
        uint32_t af[4][4];
#pragma unroll
        for (int mf = 0; mf < 4; mf++) {
            const int m0 = c.wm * 64 + mf * 16;
            const uint32_t off =
                SWZ128((uint32_t)((m0 + a_rl) * 128 + (k0 + a_cl) * 2));
            ldsm4(af[mf][0], af[mf][1], af[mf][2], af[mf][3], sA + off);
        }
#pragma unroll
        for (int mf = 0; mf < 4; mf++)
#pragma unroll
            for (int nf = 0; nf < 4; nf++)
                mma_f16(acc[mf][nf], af[mf], bf[nf]);
    }
}

__device__ __forceinline__ void hmma_mainloop(
    const HmmaCtx& c,
    const unsigned short* __restrict__ A,
    const unsigned short* __restrict__ B,
    float acc[4][4][4])
{
#pragma unroll
    for (int mf = 0; mf < 4; mf++)
#pragma unroll
        for (int nf = 0; nf < 4; nf++)
#pragma unroll
            for (int e = 0; e < 4; e++) acc[mf][nf][e] = 0.f;

    auto load_chunk = [&](int kc, int stg) {
        const uint32_t s0 = c.sbase + (uint32_t)stg * STG_BYTES;
#pragma unroll
        for (int it = 0; it < 4; it++) {
            int t = c.tid + (it << 8);
            int rr = t >> 3, ss = t & 7;
            cp16(s0 + SWZ128((uint32_t)(rr * 128 + ss * 16)),
                 A + (size_t)((c.mtile << 7) + rr) * DIM + kc * KCH + ss * 8);
        }
#pragma unroll
        for (int it = 0; it < 4; it++) {
            int t = c.tid + (it << 8);
            int rr = t >> 3, ss = t & 7;
            cp16(s0 + 16384u + SWZ128((uint32_t)(rr * 128 + ss * 16)),
                 B + (size_t)((c.ntile << 7) + rr) * DIM + kc * KCH + ss * 8);
        }
        cp_commit();
    };

    load_chunk(0, 0);
    load_chunk(1, 1);
    for (int kc = 0; kc < NKC; kc++) {
        if (kc + 1 < NKC) {
            cp_wait<1>();
        } else {
            cp_wait<0>();
        }
        __syncthreads();
        if (kc + 2 < NKC) load_chunk(kc + 2, (kc + 2) % 3);
        hmma_compute_stage(c, c.sbase + (uint32_t)(kc % 3) * STG_BYTES, acc);
    }
}

// Layer 2: out = relu(A @ B^T + bias) -> fp16
__global__ void __launch_bounds__(256, 2)
hmma_l2_kernel(const unsigned short* __restrict__ A,
               const unsigned short* __restrict__ B,
               const float* __restrict__ bias,
               unsigned short* __restrict__ outH)
{
    extern __shared__ char smem_raw[];
    HmmaCtx c;
    c.sbase = (smem_u32(smem_raw) + 127u) & ~127u;
    c.tid = threadIdx.x;
    c.lane = c.tid & 31;
    const int w = c.tid >> 5;
    c.wm = w >> 2; c.wn = w & 3;
    c.mtile = blockIdx.y; c.ntile = blockIdx.x;

    float acc[4][4][4];
    hmma_mainloop(c, A, B, acc);

    const int rl = c.lane >> 2;
    const int cl = (c.lane & 3) << 1;
#pragma unroll
    for (int mf = 0; mf < 4; mf++) {
        const int m_base = (c.mtile << 7) + c.wm * 64 + mf * 16 + rl;
#pragma unroll
        for (int nf = 0; nf < 4; nf++) {
            const int n = (c.ntile << 7) + c.wn * 32 + nf * 8 + cl;
            const float b0 = bias[n], b1 = bias[n + 1];
#pragma unroll
            for (int half = 0; half < 2; half++) {
                const int m = m_base + half * 8;
                float v0 = fmaxf(acc[mf][nf][half * 2 + 0] + b0, 0.f);
                float v1 = fmaxf(acc[mf][nf][half * 2 + 1] + b1, 0.f);
                *(uint32_t*)(outH + (size_t)m * DIM + n) =
                    (uint32_t)f2h_bits(v0) | ((uint32_t)f2h_bits(v1) << 16);
            }
        }
    }
}

// Layer 3 fused with top-18-sum -> fp16 T
#define TPAD 132
#define L3_LISTS (128 * TPAD * 4)

__global__ void __launch_bounds__(256, 2)
hmma_l3_topk_kernel(const unsigned short* __restrict__ A,
                    const unsigned short* __restrict__ B,
                    const float* __restrict__ bias,
                    unsigned short* __restrict__ TH)
{
    extern __shared__ char smem_raw[];
    HmmaCtx c;
    c.sbase = (smem_u32(smem_raw) + 127u) & ~127u;
    c.tid = threadIdx.x;
    c.lane = c.tid & 31;
    const int w = c.tid >> 5;
    c.wm = w >> 2; c.wn = w & 3;
    c.mtile = blockIdx.y; c.ntile = blockIdx.x;

    float acc[4][4][4];
    hmma_mainloop(c, A, B, acc);
    __syncthreads();

    char* sm_c = smem_raw + (c.sbase - smem_u32(smem_raw));
    float* smf = (float*)sm_c;
    const int rl = c.lane >> 2;
    const int cl = (c.lane & 3) << 1;
#pragma unroll
    for (int mf = 0; mf < 4; mf++) {
        const int ml_base = c.wm * 64 + mf * 16 + rl;
#pragma unroll
        for (int nf = 0; nf < 4; nf++) {
            const int nl = c.wn * 32 + nf * 8 + cl;
            const int n = (c.ntile << 7) + nl;
            const float b0 = bias[n], b1 = bias[n + 1];
#pragma unroll
            for (int half = 0; half < 2; half++) {
                const int ml = ml_base + half * 8;
                smf[ml * TPAD + nl] = acc[mf][nf][half * 2 + 0] + b0;
                smf[ml * TPAD + nl + 1] = acc[mf][nf][half * 2 + 1] + b1;
            }
        }
    }
    __syncthreads();

    const int cidx = c.tid & 127;
    const int half = c.tid >> 7;
    float t18[TOPK];
#pragma unroll
    for (int s = 0; s < TOPK; s++) t18[s] = -3.4e38f;
    const float* colp = smf + half * 64 * TPAD + cidx;
    for (int j = 0; j < 64; j++) {
        float v = colp[j * TPAD];
        if (v > t18[TOPK - 1]) {
            t18[TOPK - 1] = v;
#pragma unroll
            for (int s = TOPK - 1; s > 0; s--) {
                if (t18[s] > t18[s - 1]) {
                    float tmp = t18[s - 1]; t18[s - 1] = t18[s]; t18[s] = tmp;
                }
            }
        }
    }
    float* lists = (float*)(sm_c + L3_LISTS);
    if (half == 1) {
#pragma unroll
        for (int s = 0; s < TOPK; s++) lists[cidx * TOPK + s] = t18[s];
    }
    __syncthreads();
    if (half == 0) {
#pragma unroll
        for (int s = 0; s < TOPK; s++) {
            float v = lists[cidx * TOPK + s];
            if (v > t18[TOPK - 1]) {
                t18[TOPK - 1] = v;
#pragma unroll
                for (int q = TOPK - 1; q > 0; q--) {
                    if (t18[q] > t18[q - 1]) {
                        float tmp = t18[q - 1]; t18[q - 1] = t18[q]; t18[q] = tmp;
                    }
                }
            }
        }
        float sum = 0.f;
#pragma unroll
        for (int s = 0; s < TOPK; s++) sum += t18[s];
        TH[(size_t)c.mtile * DIM + (c.ntile << 7) + cidx] =
            f2h_bits(sum * 0.125f);
    }
}

// ---------------------------------------------------------------------------
// Single-K-chunk (K=64) HMMA tile: shared by layer-1 and split-K small GEMMs.
// ---------------------------------------------------------------------------
__device__ __forceinline__ void hmma_k64_tile(
    const HmmaCtx& c,
    const unsigned short* __restrict__ Abase, int KA, int aoff,
    const unsigned short* __restrict__ Bbase, int KB, int boff,
    float acc[4][4][4])
{
#pragma unroll
    for (int it = 0; it < 4; it++) {
        int t = c.tid + (it << 8);
        int rr = t >> 3, ss = t & 7;
        cp16(c.sbase + SWZ128((uint32_t)(rr * 128 + ss * 16)),
             Abase + (size_t)((c.mtile << 7) + rr) * KA + aoff + ss * 8);
    }
#pragma unroll
    for (int it = 0; it < 4; it++) {
        int t = c.tid + (it << 8);
        int rr = t >> 3, ss = t & 7;
        cp16(c.sbase + 16384u + SWZ128((uint32_t)(rr * 128 + ss * 16)),
             Bbase + (size_t)((c.ntile << 7) + rr) * KB + boff + ss * 8);
    }
    cp_commit();

#pragma unroll
    for (int mf = 0; mf < 4; mf++)
#pragma unroll
        for (int nf = 0; nf < 4; nf++)
#pragma unroll
            for (int e = 0; e < 4; e++) acc[mf][nf][e] = 0.f;

    cp_wait<0>();
    __syncthreads();
    hmma_compute_stage(c, c.sbase, acc);
}

// Layer-1: H1 = relu( G3 @ W1g^T + FA_j + FB_i + b1 )
__global__ void __launch_bounds__(256, 3)
hmma_l1_kernel(const unsigned short* __restrict__ A,
               const unsigned short* __restrict__ B,
               const float* __restrict__ bias,
               const float* __restrict__ FA,
               const float* __restrict__ FB,
               unsigned short* __restrict__ outH)
{
    extern __shared__ char smem_raw[];
    HmmaCtx c;
    c.sbase = (smem_u32(smem_raw) + 127u) & ~127u;
    c.tid = threadIdx.x;
    c.lane = c.tid & 31;
    const int w = c.tid >> 5;
    c.wm = w >> 2; c.wn = w & 3;
    c.mtile = blockIdx.y; c.ntile = blockIdx.x;

    float acc[4][4][4];
    hmma_k64_tile(c, A, GEO, 0, B, GEO, 0, acc);

    const int rl = c.lane >> 2;
    const int cl = (c.lane & 3) << 1;
#pragma unroll
    for (int mf = 0; mf < 4; mf++) {
        const int m_base = (c.mtile << 7) + c.wm * 64 + mf * 16 + rl;
#pragma unroll
        for (int nf = 0; nf < 4; nf++) {
            const int n = (c.ntile << 7) + c.wn * 32 + nf * 8 + cl;
            const float b0 = bias[n], b1 = bias[n + 1];
#pragma unroll
            for (int half = 0; half < 2; half++) {
                const int m = m_base + half * 8;
                const int j = m & (NP - 1);
                const int bi = m >> 7;
                const int bb = bi >> 7;
                const float* aJ = FA + (size_t)((bb << 7) + j) * DIM;
                const float* aI = FB + (size_t)bi * DIM;
                float v0 = acc[mf][nf][half * 2 + 0] + b0 + aJ[n] + aI[n];
                float v1 = acc[mf][nf][half * 2 + 1] + b1 + aJ[n + 1] + aI[n + 1];
                v0 = fmaxf(v0, 0.f); v1 = fmaxf(v1, 0.f);
                *(uint32_t*)(outH + (size_t)m * DIM + n) =
                    (uint32_t)f2h_bits(v0) | ((uint32_t)f2h_bits(v1) << 16);
            }
        }
    }
}

// Split-K HMMA small GEMM: P[z] = A_sel[:, slice] @ B_sel[:, slice]^T
// mode 0: A0/B0, aslice=bslice=z
// mode 1: dual-B (A0; z<NS ? B0 : B1; aslice=bslice=z%NS)   [FA/FB]
// mode 2: dual-A (z<NS ? A0 : A1, aslice=z%NS; B0 with KB, bslice=z) [ag1]
__global__ void __launch_bounds__(256, 3)
hmma_sk_kernel(const unsigned short* __restrict__ A0,
               const unsigned short* __restrict__ A1,
               const unsigned short* __restrict__ B0,
               const unsigned short* __restrict__ B1,
               float* __restrict__ P, int KB, int NS, int mode)
{
    extern __shared__ char smem_raw[];
    HmmaCtx c;
    c.sbase = (smem_u32(smem_raw) + 127u) & ~127u;
    c.tid = threadIdx.x;
    c.lane = c.tid & 31;
    const int w = c.tid >> 5;
    c.wm = w >> 2; c.wn = w & 3;
    c.mtile = blockIdx.y; c.ntile = blockIdx.x;
    const int z = blockIdx.z;

    const unsigned short* A = A0;
    const unsigned short* B = B0;
    int as = z, bs = z;
    if (mode == 1) {
        B = (z < NS) ? B0 : B1;
        as = bs = (z < NS) ? z : z - NS;
    } else if (mode == 2) {
        A = (z < NS) ? A0 : A1;
        as = (z < NS) ? z : z - NS;
    }

    float acc[4][4][4];
    hmma_k64_tile(c, A, DIM, as * KCH, B, KB, bs * KCH, acc);

    float* Pp = P + (size_t)z * MN_SMALL;
    const int rl = c.lane >> 2;
    const int cl = (c.lane & 3) << 1;
#pragma unroll
    for (int mf = 0; mf < 4; mf++) {
        const int m_base = (c.mtile << 7) + c.wm * 64 + mf * 16 + rl;
#pragma unroll
        for (int nf = 0; nf < 4; nf++) {
            const int n = (c.ntile << 7) + c.wn * 32 + nf * 8 + cl;
#pragma unroll
            for (int half = 0; half < 2; half++) {
                const int m = m_base + half * 8;
                float2 v;
                v.x = acc[mf][nf][half * 2 + 0];
                v.y = acc[mf][nf][half * 2 + 1];
                *(float2*)(Pp + (size_t)m * DIM + n) = v;
            }
        }
    }
}

// ---------------------------------------------------------------------------
// Reductions over split-K partials
// ---------------------------------------------------------------------------
__global__ __launch_bounds__(256)
void skreduce(const float* __restrict__ P, int nsl,
              const float* __restrict__ bias, int relu,
              float* __restrict__ C, int MN, int N)
{
    int idx = blockIdx.x * blockDim.x + threadIdx.x;
    if (idx >= MN) return;
    float s = 0.f;
    for (int sl = 0; sl < nsl; sl++) s += P[(size_t)sl * MN + idx];
    if (bias) s += bias[idx % N];
    if (relu) s = fmaxf(s, 0.f);
    C[idx] = s;
}

__global__ __launch_bounds__(256)
void skreduce_h(const float* __restrict__ P, int nsl,
                const float* __restrict__ bias, int relu,
                unsigned short* __restrict__ C, int MN, int N)
{
    int idx = blockIdx.x * blockDim.x + threadIdx.x;
    if (idx >= MN) return;
    float s = 0.f;
    for (int sl = 0; sl < nsl; sl++) s += P[(size_t)sl * MN + idx];
    if (bias) s += bias[idx % N];
    if (relu) s = fmaxf(s, 0.f);
    C[idx] = f2h_bits(s);
}

__global__ __launch_bounds__(256)
void skreduce_dual(const float* __restrict__ P, int nsl,
                   float* __restrict__ C0, float* __restrict__ C1, int MN)
{
    int idx = blockIdx.x * blockDim.x + threadIdx.x;
    int which = idx >= MN;
    int base = which ? nsl : 0;
    int off = which ? idx - MN : idx;
    float s = 0.f;
    for (int sl = 0; sl < nsl; sl++)
        s += P[(size_t)(base + sl) * MN + off];
    if (which) C1[off] = s; else C0[off] = s;
}

// ---------------------------------------------------------------------------
// Weight transpose + fp16 convert:  W[Kd, Nd] -> Wh [Nd, Kd]
// wsplit2: z-batched pair (same dims) in one launch.
// ---------------------------------------------------------------------------
__device__ __forceinline__ void wsplit_body(
    const float* __restrict__ W, unsigned short* __restrict__ Wh,
    int Kd, int Nd)
{
    __shared__ float tile[32][33];
    const int n0 = blockIdx.x * 32, k0 = blockIdx.y * 32;
    const int tx = threadIdx.x, ty = threadIdx.y;   // 32 x 8
#pragma unroll
    for (int i = 0; i < 32; i += 8)
        tile[ty + i][tx] = W[(size_t)(k0 + ty + i) * Nd + n0 + tx];
    __syncthreads();
#pragma unroll
    for (int i = 0; i < 32; i += 8) {
        Wh[(size_t)(n0 + ty + i) * Kd + k0 + tx] = f2h_bits(tile[tx][ty + i]);
    }
}

__global__ void wsplit_kernel(const float* __restrict__ W,
                              unsigned short* __restrict__ Wh,
                              int Kd, int Nd)
{
    wsplit_body(W, Wh, Kd, Nd);
}

__global__ void wsplit2_kernel(const float* __restrict__ Wa,
                               unsigned short* __restrict__ Wha,
                               const float* __restrict__ Wb,
                               unsigned short* __restrict__ Whb,
                               int Kd, int Nd)
{
    if (blockIdx.z == 0) wsplit_body(Wa, Wha, Kd, Nd);
    else                 wsplit_body(Wb, Whb, Kd, Nd);
}

// fp32 -> fp16 elementwise
__global__ void h_convert_kernel(const float* __restrict__ X,
                                 unsigned short* __restrict__ Xh, int n)
{
    int idx = blockIdx.x * blockDim.x + threadIdx.x;
    if (idx < n) Xh[idx] = f2h_bits(X[idx]);
}

// ---------------------------------------------------------------------------
// Geo embedding + 3-layer 64-wide MLP (fused) -> fp16 output
// ---------------------------------------------------------------------------
__global__ __launch_bounds__(128)
void geo_kernel(const float* __restrict__ prop,
                const float* __restrict__ w1, const float* __restrict__ b1,
                const float* __restrict__ w2, const float* __restrict__ b2,
                const float* __restrict__ w3, const float* __restrict__ b3,
                unsigned short* __restrict__ G3)
{
    __shared__ float sw1[GEO * GEO], sw2[GEO * GEO], sw3[GEO * GEO];
    __shared__ float sb1[GEO], sb2[GEO], sb3[GEO];
    __shared__ float esm[128 * 65];

    const int tid = threadIdx.x;
    for (int t = tid; t < GEO * GEO; t += blockDim.x) {
        sw1[t] = w1[t]; sw2[t] = w2[t]; sw3[t] = w3[t];
    }
    for (int t = tid; t < GEO; t += blockDim.x) {
        sb1[t] = b1[t]; sb2[t] = b2[t]; sb3[t] = b3[t];
    }
    __syncthreads();

    const int row = blockIdx.x * blockDim.x + tid;
    const int b = row >> 14;
    const int i = (row >> 7) & (NP - 1);
    const int j = row & (NP - 1);

    const float* pi = prop + ((size_t)(b * NP + i)) * 4;
    const float* pj = prop + ((size_t)(b * NP + j)) * 4;
    float wi = pi[2] - pi[0] + 1.f, hi = pi[3] - pi[1] + 1.f;
    float wj = pj[2] - pj[0] + 1.f, hj = pj[3] - pj[1] + 1.f;
    float cxi = 0.5f * (pi[0] + pi[2]), cyi = 0.5f * (pi[1] + pi[3]);
    float cxj = 0.5f * (pj[0] + pj[2]), cyj = 0.5f * (pj[1] + pj[3]);

    float pos[4];
    pos[0] = (cxi - cxj) / wj;
    pos[1] = (cyi - cyj) / hj;
    pos[2] = wi / wj;
    pos[3] = hi / hj;

    const float dm[8] = {1.0f, 2.3713737f, 5.6234133f, 13.335215f,
                         31.622777f, 74.989421f, 177.82794f, 421.69650f};

    float* my = &esm[tid * 65];
#pragma unroll
    for (int p = 0; p < 4; p++) {
        float lp = logf(fmaxf(fabsf(pos[p]), 1e-3f)) * 100.f;
#pragma unroll
        for (int r = 0; r < 8; r++) {
            float arg = lp / dm[r];
            float s, cc;
            sincosf(arg, &s, &cc);
            my[p * 16 + r] = s;
            my[p * 16 + 8 + r] = cc;
        }
    }

    float acc[GEO];
#pragma unroll
    for (int o = 0; o < GEO; o++) acc[o] = sb1[o];
    for (int k = 0; k < GEO; k++) {
        float ek = my[k];
        const float* wr = &sw1[k * GEO];
#pragma unroll
        for (int o = 0; o < GEO; o++) acc[o] = fmaf(ek, wr[o], acc[o]);
    }
#pragma unroll
    for (int o = 0; o < GEO; o++) my[o] = fmaxf(acc[o], 0.f);

#pragma unroll
    for (int o = 0; o < GEO; o++) acc[o] = sb2[o];
    for (int k = 0; k < GEO; k++) {
        float ek = my[k];
        const float* wr = &sw2[k * GEO];
#pragma unroll
        for (int o = 0; o < GEO; o++) acc[o] = fmaf(ek, wr[o], acc[o]);
    }
#pragma unroll
    for (int o = 0; o < GEO; o++) my[o] = fmaxf(acc[o], 0.f);

#pragma unroll
    for (int o = 0; o < GEO; o++) acc[o] = sb3[o];
    for (int k = 0; k < GEO; k++) {
        float ek = my[k];
        const float* wr = &sw3[k * GEO];
#pragma unroll
        for (int o = 0; o < GEO; o++) acc[o] = fmaf(ek, wr[o], acc[o]);
    }
    unsigned short* outp = G3 + (size_t)row * GEO;
#pragma unroll
    for (int o = 0; o < GEO; o++) outp[o] = f2h_bits(acc[o]);
}

// ---------------------------------------------------------------------------
// heads
// ---------------------------------------------------------------------------
__global__ __launch_bounds__(128)
void heads_kernel(const float* __restrict__ X,
                  const float* __restrict__ subject,
                  const float* __restrict__ obj,
                  const float* __restrict__ cs_w, const float* __restrict__ cs_b,
                  const float* __restrict__ cso_w, const float* __restrict__ cso_b,
                  float* __restrict__ out)
{
    int row = blockIdx.x;
    int b = row >> 7;
    int tid = threadIdx.x;

    float as = 0.f, ao = 0.f;
    for (int k = tid; k < DIM; k += 128) {
        float xv = X[(size_t)row * DIM + k];
        float sv = subject[(size_t)b * DIM + k];
        float ov = obj[(size_t)b * DIM + k];
        as += xv * cs_w[k] + sv * cs_w[DIM + k];
        ao += xv * cso_w[k] + ov * cso_w[DIM + k];
    }
    __shared__ float rs[128], ro[128];
    rs[tid] = as; ro[tid] = ao;
    __syncthreads();
    for (int s = 64; s > 0; s >>= 1) {
        if (tid < s) { rs[tid] += rs[tid + s]; ro[tid] += ro[tid + s]; }
        __syncthreads();
    }
    if (tid == 0) {
        float s1 = rs[0] + cs_b[0];
        float s2 = ro[0] + cso_b[0];
        out[row * 2 + 0] = 1.f / (1.f + expf(-s1));
        out[row * 2 + 1] = 1.f / (1.f + expf(-s2));
    }
}

// ---------------------------------------------------------------------------
// Launch (R15 fork topology + R14 split-K small GEMMs + batched wsplits)
// ---------------------------------------------------------------------------
extern "C" void kernel_launch(void* const* d_in, const int* in_sizes, int n_in,
                              void* d_out, int out_size)
{
    const float* feats   = (const float*)d_in[0];
    const float* subject = (const float*)d_in[1];
    const float* obj     = (const float*)d_in[2];
    const float* prop    = (const float*)d_in[3];
    const float* gp_w1 = (const float*)d_in[4];
    const float* gp_b1 = (const float*)d_in[5];
    const float* gp_w2 = (const float*)d_in[6];
    const float* gp_b2 = (const float*)d_in[7];
    const float* gp_w3 = (const float*)d_in[8];
    const float* gp_b3 = (const float*)d_in[9];
    const float* pm_w1 = (const float*)d_in[10];
    const float* pm_b1 = (const float*)d_in[11];
    const float* pm_w2 = (const float*)d_in[12];
    const float* pm_b2 = (const float*)d_in[13];
    const float* pm_w3 = (const float*)d_in[14];
    const float* pm_b3 = (const float*)d_in[15];
    const float* ag_w1 = (const float*)d_in[16];
    const float* ag_b1 = (const float*)d_in[17];
    const float* ag_w2 = (const float*)d_in[18];
    const float* ag_b2 = (const float*)d_in[19];
    const float* ag_w3 = (const float*)d_in[20];
    const float* ag_b3 = (const float*)d_in[21];
    const float* cs_w  = (const float*)d_in[22];
    const float* cs_b  = (const float*)d_in[23];
    const float* cso_w = (const float*)d_in[24];
    const float* cso_b = (const float*)d_in[25];
    float* out = (float*)d_out;

    float *FA, *FB, *SA, *P;
    unsigned short *featsH, *TH, *SAh, *SBh;
    unsigned short *G3, *H1, *H2, *W1, *W2, *W3, *WFA, *WFB, *AG1, *AG2, *AG3;
    cudaGetSymbolAddress((void**)&FA, g_FA);
    cudaGetSymbolAddress((void**)&FB, g_FB);
    cudaGetSymbolAddress((void**)&SA, g_SA);
    cudaGetSymbolAddress((void**)&P,  g_P);
    cudaGetSymbolAddress((void**)&featsH, g_featsH);
    cudaGetSymbolAddress((void**)&TH, g_TH);
    cudaGetSymbolAddress((void**)&SAh, g_SAh);
    cudaGetSymbolAddress((void**)&SBh, g_SBh);
    cudaGetSymbolAddress((void**)&G3, g_G3);
    cudaGetSymbolAddress((void**)&H1, g_H1);
    cudaGetSymbolAddress((void**)&H2, g_H2);
    cudaGetSymbolAddress((void**)&W1, g_W1);
    cudaGetSymbolAddress((void**)&W2, g_W2);
    cudaGetSymbolAddress((void**)&W3, g_W3);
    cudaGetSymbolAddress((void**)&WFA, g_WFA);
    cudaGetSymbolAddress((void**)&WFB, g_WFB);
    cudaGetSymbolAddress((void**)&AG1, g_AG1);
    cudaGetSymbolAddress((void**)&AG2, g_AG2);
    cudaGetSymbolAddress((void**)&AG3, g_AG3);

    cudaFuncSetAttribute(hmma_l2_kernel,
                         cudaFuncAttributeMaxDynamicSharedMemorySize, HMMA_SMEM);
    cudaFuncSetAttribute(hmma_l3_topk_kernel,
                         cudaFuncAttributeMaxDynamicSharedMemorySize, HMMA_SMEM);
    cudaFuncSetAttribute(hmma_l1_kernel,
                         cudaFuncAttributeMaxDynamicSharedMemorySize, L1_SMEM);
    cudaFuncSetAttribute(hmma_sk_kernel,
                         cudaFuncAttributeMaxDynamicSharedMemorySize, L1_SMEM);

    dim3 ghm(DIM / 128, MBIG / 128);          // (8, 256)
    dim3 gws(DIM / 32, DIM / 32);
    dim3 gws2(DIM / 32, DIM / 32, 2);
    dim3 gws1(DIM / 32, GEO / 32);
    const int MN = MN_SMALL;

    // ---- forked prologue ----
    cudaStream_t s1;
    cudaEvent_t eFork, eJoin, eJoin2, eJoin3;
    bool forked =
        (cudaStreamCreateWithFlags(&s1, cudaStreamNonBlocking) == cudaSuccess) &&
        (cudaEventCreateWithFlags(&eFork, cudaEventDisableTiming) == cudaSuccess) &&
        (cudaEventCreateWithFlags(&eJoin, cudaEventDisableTiming) == cudaSuccess) &&
        (cudaEventCreateWithFlags(&eJoin2, cudaEventDisableTiming) == cudaSuccess) &&
        (cudaEventCreateWithFlags(&eJoin3, cudaEventDisableTiming) == cudaSuccess);

    if (forked) forked = (cudaEventRecord(eFork, 0) == cudaSuccess) &&
                         (cudaStreamWaitEvent(s1, eFork, 0) == cudaSuccess);

    cudaStream_t sb = forked ? s1 : 0;

    // branch B: geo first (l1 dep) -> join1; W2/W3 (l2/l3 dep) -> join2;
    // AG converts -> join3 (overlap with l1/l2/l3)
    geo_kernel<<<MBIG / 128, 128, 0, sb>>>(prop, gp_w1, gp_b1, gp_w2, gp_b2,
                                           gp_w3, gp_b3, G3);
    if (forked) cudaEventRecord(eJoin, s1);
    wsplit2_kernel<<<gws2, dim3(32, 8), 0, sb>>>(pm_w2, W2, pm_w3, W3,
                                                 DIM, DIM);
    if (forked) cudaEventRecord(eJoin2, s1);
    wsplit_kernel<<<dim3(DIM / 32, 2 * DIM / 32), dim3(32, 8), 0, sb>>>(
        ag_w1, AG1, 2 * DIM, DIM);
    wsplit2_kernel<<<gws2, dim3(32, 8), 0, sb>>>(ag_w2, AG2, ag_w3, AG3,
                                                 DIM, DIM);
    if (forked) cudaEventRecord(eJoin3, s1);

    // main branch: converts + FA/FB split-K HMMA
    h_convert_kernel<<<MN / 256, 256>>>(feats, featsH, MN);
    wsplit_kernel<<<gws1, dim3(32, 8)>>>(pm_w1 + (size_t)2 * DIM * DIM,
                                         W1, GEO, DIM);
    wsplit2_kernel<<<gws2, dim3(32, 8)>>>(pm_w1, WFA,
                                          pm_w1 + (size_t)DIM * DIM, WFB,
                                          DIM, DIM);
    dim3 gsk32(DIM / 128, MSMALL / 128, 32);   // (8, 2, 32)
    hmma_sk_kernel<<<gsk32, 256, L1_SMEM>>>(featsH, nullptr, WFA, WFB,
                                            P, DIM, 16, 1);
    skreduce_dual<<<(2 * MN) / 256, 256>>>(P, 16, FA, FB, MN);

    if (forked) cudaStreamWaitEvent(0, eJoin, 0);

    // Pairwise layer 1 (fp16 HMMA, K=64) -> H1 fp16
    hmma_l1_kernel<<<ghm, 256, L1_SMEM>>>(G3, W1, pm_b1, FA, FB, H1);

    if (forked) cudaStreamWaitEvent(0, eJoin2, 0);

    // Pairwise layer 2 (fp16 HMMA) -> H2 fp16, relu
    hmma_l2_kernel<<<ghm, 256, HMMA_SMEM>>>(H1, W2, pm_b2, H2);
    // Pairwise layer 3 + fused top-18 sum -> TH fp16
    hmma_l3_topk_kernel<<<ghm, 256, HMMA_SMEM>>>(H2, W3, pm_b3, TH);

    if (forked) cudaStreamWaitEvent(0, eJoin3, 0);

    // Aggregate MLP via HMMA split-K; ag1 = [featsH | TH] @ AG1 (dual-A)
    dim3 gsk16(DIM / 128, MSMALL / 128, 16);
    hmma_sk_kernel<<<gsk32, 256, L1_SMEM>>>(featsH, TH, AG1, nullptr,
                                            P, 2 * DIM, 16, 2);
    skreduce_h<<<MN / 256, 256>>>(P, 32, ag_b1, 1, SAh, MN, DIM);
    hmma_sk_kernel<<<gsk16, 256, L1_SMEM>>>(SAh, nullptr, AG2, nullptr,
                                            P, DIM, 16, 0);
    skreduce_h<<<MN / 256, 256>>>(P, 16, ag_b2, 1, SBh, MN, DIM);
    hmma_sk_kernel<<<gsk16, 256, L1_SMEM>>>(SBh, nullptr, AG3, nullptr,
                                            P, DIM, 16, 0);
    skreduce<<<MN / 256, 256>>>(P, 16, ag_b3, 0, SA, MN, DIM);

    // Heads
    heads_kernel<<<MSMALL, 128>>>(SA, subject, obj, cs_w, cs_b, cso_w, cso_b, out);
}

// round 17
// speedup vs baseline: 1.0726x; 1.0283x over previous
#include <cuda_runtime.h>
#include <cuda_fp16.h>
#include <cstdint>
#include <cstddef>

// ---------------------------------------------------------------------------
// Problem constants
// ---------------------------------------------------------------------------
#define BSZ 2
#define NP  128
#define DIM 1024
#define GEO 64
#define TOPK 18
#define MBIG (BSZ * NP * NP)     // 32768 pairwise rows
#define MSMALL (BSZ * NP)        // 256 proposal rows
#define MN_SMALL (MSMALL * DIM)  // 262144

// ---------------------------------------------------------------------------
// Scratch (static device globals)
// ---------------------------------------------------------------------------
__device__ float g_SA[MN_SMALL];
__device__ float g_P[32 * MN_SMALL];             // split-K partials (32 MB)
__device__ unsigned short g_FAh[MN_SMALL];       // FA fp16
__device__ unsigned short g_FBh[MN_SMALL];       // FB fp16
__device__ unsigned short g_featsH[MN_SMALL];    // feats fp16
__device__ unsigned short g_TH[MN_SMALL];        // topk out fp16
__device__ unsigned short g_SAh[MN_SMALL];
__device__ unsigned short g_SBh[MN_SMALL];
__device__ unsigned short g_G3[MBIG * GEO];      // geo out fp16 (4 MB)
__device__ unsigned short g_H1[(size_t)MBIG * DIM];  // fp16, 64 MB
__device__ unsigned short g_H2[(size_t)MBIG * DIM];  // fp16, 64 MB
__device__ unsigned short g_W1[DIM * GEO];       // [N,K] w1 geo slice fp16
__device__ unsigned short g_W2[DIM * DIM];       // [N,K] fp16
__device__ unsigned short g_W3[DIM * DIM];       // [N,K] fp16
__device__ unsigned short g_WFA[DIM * DIM];      // pm_w1[0:1024] -> [N,K]
__device__ unsigned short g_WFB[DIM * DIM];      // pm_w1[1024:2048] -> [N,K]
__device__ unsigned short g_AG1[DIM * 2 * DIM];  // ag_w1 -> [1024, 2048]
__device__ unsigned short g_AG2[DIM * DIM];
__device__ unsigned short g_AG3[DIM * DIM];

// ---------------------------------------------------------------------------
// Helpers (sm_80+ only: cp.async, ldmatrix, mma.sync)
// ---------------------------------------------------------------------------
__device__ __forceinline__ uint32_t smem_u32(const void* p) {
    uint32_t a;
    asm("{ .reg .u64 t; cvta.to.shared.u64 t, %1; cvt.u32.u64 %0, t; }"
        : "=r"(a) : "l"(p));
    return a;
}
__device__ __forceinline__ void cp16(uint32_t dst, const void* src) {
    asm volatile("cp.async.cg.shared.global [%0], [%1], 16;" :: "r"(dst), "l"(src));
}
__device__ __forceinline__ void cp_commit() {
    asm volatile("cp.async.commit_group;" ::: "memory");
}
template<int N> __device__ __forceinline__ void cp_wait() {
    asm volatile("cp.async.wait_group %0;" :: "n"(N) : "memory");
}
#define SWZ128(o) ((o) ^ (((o) >> 3) & 0x70))

__device__ __forceinline__ void ldsm4(uint32_t& r0, uint32_t& r1,
                                      uint32_t& r2, uint32_t& r3, uint32_t addr) {
    asm volatile("ldmatrix.sync.aligned.m8n8.x4.shared.b16 {%0,%1,%2,%3}, [%4];"
                 : "=r"(r0), "=r"(r1), "=r"(r2), "=r"(r3) : "r"(addr));
}
__device__ __forceinline__ void mma_f16(float* c,
                                        const uint32_t* a, const uint32_t* b) {
    asm volatile("mma.sync.aligned.m16n8k16.row.col.f32.f16.f16.f32 "
                 "{%0,%1,%2,%3}, {%4,%5,%6,%7}, {%8,%9}, {%0,%1,%2,%3};"
                 : "+f"(c[0]), "+f"(c[1]), "+f"(c[2]), "+f"(c[3])
                 : "r"(a[0]), "r"(a[1]), "r"(a[2]), "r"(a[3]),
                   "r"(b[0]), "r"(b[1]));
}

__device__ __forceinline__ unsigned short f2h_bits(float v) {
    __half h = __float2half_rn(v);
    return *reinterpret_cast<unsigned short*>(&h);
}
__device__ __forceinline__ float h_bits2f(unsigned short u) {
    __half h = *reinterpret_cast<__half*>(&u);
    return __half2float(h);
}

// ---------------------------------------------------------------------------
// fp16 HMMA mainloop (128x128 CTA tile; 8 warps 2(M)x4(N); warp tile 64x32).
// Single __syncthreads per k-chunk.
// ---------------------------------------------------------------------------
#define KCH 64
#define NKC (DIM / KCH)            // 16
#define STG_BYTES 32768
#define HMMA_SMEM (3 * STG_BYTES + 128)
#define L1_SMEM (2 * 16384 + 128)

struct HmmaCtx {
    uint32_t sbase;
    int tid, lane, wm, wn, mtile, ntile;
};

__device__ __forceinline__ void hmma_compute_stage(
    const HmmaCtx& c, uint32_t s0, float acc[4][4][4])
{
    const int a_rl = c.lane & 15;
    const int a_cl = (c.lane >> 4) << 3;
    const int b_rl = (c.lane & 7) + ((c.lane >> 4) << 3);
    const int b_cl = ((c.lane >> 3) & 1) << 3;
    const uint32_t sA = s0, sB = s0 + 16384u;
#pragma unroll
    for (int ks = 0; ks < 4; ks++) {
        const int k0 = ks * 16;
        uint32_t bf[4][2];
#pragma unroll
        for (int np = 0; np < 2; np++) {
            const int n0 = c.wn * 32 + np * 16;
            const uint32_t off =
                SWZ128((uint32_t)((n0 + b_rl) * 128 + (k0 + b_cl) * 2));
            uint32_t r0, r1, r2, r3;
            ldsm4(r0, r1, r2, r3, sB + off);
            bf[np * 2][0] = r0; bf[np * 2][1] = r1;
            bf[np * 2 + 1][0] = r2; bf[np * 2 + 1][1] = r3;
        }
        uint32_t af[4][4];
#pragma unroll
        for (int mf = 0; mf < 4; mf++) {
            const int m0 = c.wm * 64 + mf * 16;
            const uint32_t off =
                SWZ128((uint32_t)((m0 + a_rl) * 128 + (k0 + a_cl) * 2));
            ldsm4(af[mf][0], af[mf][1], af[mf][2], af[mf][3], sA + off);
        }
#pragma unroll
        for (int mf = 0; mf < 4; mf++)
#pragma unroll
            for (int nf = 0; nf < 4; nf++)
                mma_f16(acc[mf][nf], af[mf], bf[nf]);
    }
}

__device__ __forceinline__ void hmma_mainloop(
    const HmmaCtx& c,
    const unsigned short* __restrict__ A,
    const unsigned short* __restrict__ B,
    float acc[4][4][4])
{
#pragma unroll
    for (int mf = 0; mf < 4; mf++)
#pragma unroll
        for (int nf = 0; nf < 4; nf++)
#pragma unroll
            for (int e = 0; e < 4; e++) acc[mf][nf][e] = 0.f;

    auto load_chunk = [&](int kc, int stg) {
        const uint32_t s0 = c.sbase + (uint32_t)stg * STG_BYTES;
#pragma unroll
        for (int it = 0; it < 4; it++) {
            int t = c.tid + (it << 8);
            int rr = t >> 3, ss = t & 7;
            cp16(s0 + SWZ128((uint32_t)(rr * 128 + ss * 16)),
                 A + (size_t)((c.mtile << 7) + rr) * DIM + kc * KCH + ss * 8);
        }
#pragma unroll
        for (int it = 0; it < 4; it++) {
            int t = c.tid + (it << 8);
            int rr = t >> 3, ss = t & 7;
            cp16(s0 + 16384u + SWZ128((uint32_t)(rr * 128 + ss * 16)),
                 B + (size_t)((c.ntile << 7) + rr) * DIM + kc * KCH + ss * 8);
        }
        cp_commit();
    };

    load_chunk(0, 0);
    load_chunk(1, 1);
    for (int kc = 0; kc < NKC; kc++) {
        if (kc + 1 < NKC) {
            cp_wait<1>();
        } else {
            cp_wait<0>();
        }
        __syncthreads();
        if (kc + 2 < NKC) load_chunk(kc + 2, (kc + 2) % 3);
        hmma_compute_stage(c, c.sbase + (uint32_t)(kc % 3) * STG_BYTES, acc);
    }
}

// Layer 2: out = relu(A @ B^T + bias) -> fp16. mtile_off for half-launches.
__global__ void __launch_bounds__(256, 2)
hmma_l2_kernel(const unsigned short* __restrict__ A,
               const unsigned short* __restrict__ B,
               const float* __restrict__ bias,
               unsigned short* __restrict__ outH, int mtile_off)
{
    extern __shared__ char smem_raw[];
    HmmaCtx c;
    c.sbase = (smem_u32(smem_raw) + 127u) & ~127u;
    c.tid = threadIdx.x;
    c.lane = c.tid & 31;
    const int w = c.tid >> 5;
    c.wm = w >> 2; c.wn = w & 3;
    c.mtile = blockIdx.y + mtile_off; c.ntile = blockIdx.x;

    float acc[4][4][4];
    hmma_mainloop(c, A, B, acc);

    const int rl = c.lane >> 2;
    const int cl = (c.lane & 3) << 1;
#pragma unroll
    for (int mf = 0; mf < 4; mf++) {
        const int m_base = (c.mtile << 7) + c.wm * 64 + mf * 16 + rl;
#pragma unroll
        for (int nf = 0; nf < 4; nf++) {
            const int n = (c.ntile << 7) + c.wn * 32 + nf * 8 + cl;
            const float b0 = bias[n], b1 = bias[n + 1];
#pragma unroll
            for (int half = 0; half < 2; half++) {
                const int m = m_base + half * 8;
                float v0 = fmaxf(acc[mf][nf][half * 2 + 0] + b0, 0.f);
                float v1 = fmaxf(acc[mf][nf][half * 2 + 1] + b1, 0.f);
                *(uint32_t*)(outH + (size_t)m * DIM + n) =
                    (uint32_t)f2h_bits(v0) | ((uint32_t)f2h_bits(v1) << 16);
            }
        }
    }
}

// Layer 3 fused with top-18-sum -> fp16 T. mtile_off for half-launches.
#define TPAD 132
#define L3_LISTS (128 * TPAD * 4)

__global__ void __launch_bounds__(256, 2)
hmma_l3_topk_kernel(const unsigned short* __restrict__ A,
                    const unsigned short* __restrict__ B,
                    const float* __restrict__ bias,
                    unsigned short* __restrict__ TH, int mtile_off)
{
    extern __shared__ char smem_raw[];
    HmmaCtx c;
    c.sbase = (smem_u32(smem_raw) + 127u) & ~127u;
    c.tid = threadIdx.x;
    c.lane = c.tid & 31;
    const int w = c.tid >> 5;
    c.wm = w >> 2; c.wn = w & 3;
    c.mtile = blockIdx.y + mtile_off; c.ntile = blockIdx.x;

    float acc[4][4][4];
    hmma_mainloop(c, A, B, acc);
    __syncthreads();

    char* sm_c = smem_raw + (c.sbase - smem_u32(smem_raw));
    float* smf = (float*)sm_c;
    const int rl = c.lane >> 2;
    const int cl = (c.lane & 3) << 1;
#pragma unroll
    for (int mf = 0; mf < 4; mf++) {
        const int ml_base = c.wm * 64 + mf * 16 + rl;
#pragma unroll
        for (int nf = 0; nf < 4; nf++) {
            const int nl = c.wn * 32 + nf * 8 + cl;
            const int n = (c.ntile << 7) + nl;
            const float b0 = bias[n], b1 = bias[n + 1];
#pragma unroll
            for (int half = 0; half < 2; half++) {
                const int ml = ml_base + half * 8;
                smf[ml * TPAD + nl] = acc[mf][nf][half * 2 + 0] + b0;
                smf[ml * TPAD + nl + 1] = acc[mf][nf][half * 2 + 1] + b1;
            }
        }
    }
    __syncthreads();

    const int cidx = c.tid & 127;
    const int half = c.tid >> 7;
    float t18[TOPK];
#pragma unroll
    for (int s = 0; s < TOPK; s++) t18[s] = -3.4e38f;
    const float* colp = smf + half * 64 * TPAD + cidx;
    for (int j = 0; j < 64; j++) {
        float v = colp[j * TPAD];
        if (v > t18[TOPK - 1]) {
            t18[TOPK - 1] = v;
#pragma unroll
            for (int s = TOPK - 1; s > 0; s--) {
                if (t18[s] > t18[s - 1]) {
                    float tmp = t18[s - 1]; t18[s - 1] = t18[s]; t18[s] = tmp;
                }
            }
        }
    }
    float* lists = (float*)(sm_c + L3_LISTS);
    if (half == 1) {
#pragma unroll
        for (int s = 0; s < TOPK; s++) lists[cidx * TOPK + s] = t18[s];
    }
    __syncthreads();
    if (half == 0) {
#pragma unroll
        for (int s = 0; s < TOPK; s++) {
            float v = lists[cidx * TOPK + s];
            if (v > t18[TOPK - 1]) {
                t18[TOPK - 1] = v;
#pragma unroll
                for (int q = TOPK - 1; q > 0; q--) {
                    if (t18[q] > t18[q - 1]) {
                        float tmp = t18[q - 1]; t18[q - 1] = t18[q]; t18[q] = tmp;
                    }
                }
            }
        }
        float sum = 0.f;
#pragma unroll
        for (int s = 0; s < TOPK; s++) sum += t18[s];
        TH[(size_t)c.mtile * DIM + (c.ntile << 7) + cidx] =
            f2h_bits(sum * 0.125f);
    }
}

// ---------------------------------------------------------------------------
// Single-K-chunk (K=64) HMMA tile
// ---------------------------------------------------------------------------
__device__ __forceinline__ void hmma_k64_tile(
    const HmmaCtx& c,
    const unsigned short* __restrict__ Abase, int KA, int aoff,
    const unsigned short* __restrict__ Bbase, int KB, int boff,
    float acc[4][4][4])
{
#pragma unroll
    for (int it = 0; it < 4; it++) {
        int t = c.tid + (it << 8);
        int rr = t >> 3, ss = t & 7;
        cp16(c.sbase + SWZ128((uint32_t)(rr * 128 + ss * 16)),
             Abase + (size_t)((c.mtile << 7) + rr) * KA + aoff + ss * 8);
    }
#pragma unroll
    for (int it = 0; it < 4; it++) {
        int t = c.tid + (it << 8);
        int rr = t >> 3, ss = t & 7;
        cp16(c.sbase + 16384u + SWZ128((uint32_t)(rr * 128 + ss * 16)),
             Bbase + (size_t)((c.ntile << 7) + rr) * KB + boff + ss * 8);
    }
    cp_commit();

#pragma unroll
    for (int mf = 0; mf < 4; mf++)
#pragma unroll
        for (int nf = 0; nf < 4; nf++)
#pragma unroll
            for (int e = 0; e < 4; e++) acc[mf][nf][e] = 0.f;

    cp_wait<0>();
    __syncthreads();
    hmma_compute_stage(c, c.sbase, acc);
}

// Layer-1: H1 = relu( G3 @ W1g^T + FA_j + FB_i + b1 )   (FA/FB fp16)
__global__ void __launch_bounds__(256, 3)
hmma_l1_kernel(const unsigned short* __restrict__ A,
               const unsigned short* __restrict__ B,
               const float* __restrict__ bias,
               const unsigned short* __restrict__ FAh,
               const unsigned short* __restrict__ FBh,
               unsigned short* __restrict__ outH)
{
    extern __shared__ char smem_raw[];
    HmmaCtx c;
    c.sbase = (smem_u32(smem_raw) + 127u) & ~127u;
    c.tid = threadIdx.x;
    c.lane = c.tid & 31;
    const int w = c.tid >> 5;
    c.wm = w >> 2; c.wn = w & 3;
    c.mtile = blockIdx.y; c.ntile = blockIdx.x;

    float acc[4][4][4];
    hmma_k64_tile(c, A, GEO, 0, B, GEO, 0, acc);

    const int rl = c.lane >> 2;
    const int cl = (c.lane & 3) << 1;
#pragma unroll
    for (int mf = 0; mf < 4; mf++) {
        const int m_base = (c.mtile << 7) + c.wm * 64 + mf * 16 + rl;
#pragma unroll
        for (int nf = 0; nf < 4; nf++) {
            const int n = (c.ntile << 7) + c.wn * 32 + nf * 8 + cl;
            const float b0 = bias[n], b1 = bias[n + 1];
#pragma unroll
            for (int half = 0; half < 2; half++) {
                const int m = m_base + half * 8;
                const int j = m & (NP - 1);
                const int bi = m >> 7;
                const int bb = bi >> 7;
                uint32_t aj = *(const uint32_t*)(
                    FAh + (size_t)((bb << 7) + j) * DIM + n);
                uint32_t ai = *(const uint32_t*)(
                    FBh + (size_t)bi * DIM + n);
                float v0 = acc[mf][nf][half * 2 + 0] + b0
                         + h_bits2f((unsigned short)(aj & 0xFFFF))
                         + h_bits2f((unsigned short)(ai & 0xFFFF));
                float v1 = acc[mf][nf][half * 2 + 1] + b1
                         + h_bits2f((unsigned short)(aj >> 16))
                         + h_bits2f((unsigned short)(ai >> 16));
                v0 = fmaxf(v0, 0.f); v1 = fmaxf(v1, 0.f);
                *(uint32_t*)(outH + (size_t)m * DIM + n) =
                    (uint32_t)f2h_bits(v0) | ((uint32_t)f2h_bits(v1) << 16);
            }
        }
    }
}

// Split-K HMMA small GEMM (modes as R16)
__global__ void __launch_bounds__(256, 3)
hmma_sk_kernel(const unsigned short* __restrict__ A0,
               const unsigned short* __restrict__ A1,
               const unsigned short* __restrict__ B0,
               const unsigned short* __restrict__ B1,
               float* __restrict__ P, int KB, int NS, int mode)
{
    extern __shared__ char smem_raw[];
    HmmaCtx c;
    c.sbase = (smem_u32(smem_raw) + 127u) & ~127u;
    c.tid = threadIdx.x;
    c.lane = c.tid & 31;
    const int w = c.tid >> 5;
    c.wm = w >> 2; c.wn = w & 3;
    c.mtile = blockIdx.y; c.ntile = blockIdx.x;
    const int z = blockIdx.z;

    const unsigned short* A = A0;
    const unsigned short* B = B0;
    int as = z, bs = z;
    if (mode == 1) {
        B = (z < NS) ? B0 : B1;
        as = bs = (z < NS) ? z : z - NS;
    } else if (mode == 2) {
        A = (z < NS) ? A0 : A1;
        as = (z < NS) ? z : z - NS;
    }

    float acc[4][4][4];
    hmma_k64_tile(c, A, DIM, as * KCH, B, KB, bs * KCH, acc);

    float* Pp = P + (size_t)z * MN_SMALL;
    const int rl = c.lane >> 2;
    const int cl = (c.lane & 3) << 1;
#pragma unroll
    for (int mf = 0; mf < 4; mf++) {
        const int m_base = (c.mtile << 7) + c.wm * 64 + mf * 16 + rl;
#pragma unroll
        for (int nf = 0; nf < 4; nf++) {
            const int n = (c.ntile << 7) + c.wn * 32 + nf * 8 + cl;
#pragma unroll
            for (int half = 0; half < 2; half++) {
                const int m = m_base + half * 8;
                float2 v;
                v.x = acc[mf][nf][half * 2 + 0];
                v.y = acc[mf][nf][half * 2 + 1];
                *(float2*)(Pp + (size_t)m * DIM + n) = v;
            }
        }
    }
}

// ---------------------------------------------------------------------------
// Reductions over split-K partials
// ---------------------------------------------------------------------------
__global__ __launch_bounds__(256)
void skreduce(const float* __restrict__ P, int nsl,
              const float* __restrict__ bias, int relu,
              float* __restrict__ C, int MN, int N)
{
    int idx = blockIdx.x * blockDim.x + threadIdx.x;
    if (idx >= MN) return;
    float s = 0.f;
    for (int sl = 0; sl < nsl; sl++) s += P[(size_t)sl * MN + idx];
    if (bias) s += bias[idx % N];
    if (relu) s = fmaxf(s, 0.f);
    C[idx] = s;
}

__global__ __launch_bounds__(256)
void skreduce_h(const float* __restrict__ P, int nsl,
                const float* __restrict__ bias, int relu,
                unsigned short* __restrict__ C, int MN, int N)
{
    int idx = blockIdx.x * blockDim.x + threadIdx.x;
    if (idx >= MN) return;
    float s = 0.f;
    for (int sl = 0; sl < nsl; sl++) s += P[(size_t)sl * MN + idx];
    if (bias) s += bias[idx % N];
    if (relu) s = fmaxf(s, 0.f);
    C[idx] = f2h_bits(s);
}

// dual reduce -> fp16 outputs (FA/FB)
__global__ __launch_bounds__(256)
void skreduce_dual_h(const float* __restrict__ P, int nsl,
                     unsigned short* __restrict__ C0,
                     unsigned short* __restrict__ C1, int MN)
{
    int idx = blockIdx.x * blockDim.x + threadIdx.x;
    int which = idx >= MN;
    int base = which ? nsl : 0;
    int off = which ? idx - MN : idx;
    float s = 0.f;
    for (int sl = 0; sl < nsl; sl++)
        s += P[(size_t)(base + sl) * MN + off];
    if (which) C1[off] = f2h_bits(s); else C0[off] = f2h_bits(s);
}

// ---------------------------------------------------------------------------
// Weight transpose + fp16 convert
// ---------------------------------------------------------------------------
__device__ __forceinline__ void wsplit_body(
    const float* __restrict__ W, unsigned short* __restrict__ Wh,
    int Kd, int Nd)
{
    __shared__ float tile[32][33];
    const int n0 = blockIdx.x * 32, k0 = blockIdx.y * 32;
    const int tx = threadIdx.x, ty = threadIdx.y;   // 32 x 8
#pragma unroll
    for (int i = 0; i < 32; i += 8)
        tile[ty + i][tx] = W[(size_t)(k0 + ty + i) * Nd + n0 + tx];
    __syncthreads();
#pragma unroll
    for (int i = 0; i < 32; i += 8) {
        Wh[(size_t)(n0 + ty + i) * Kd + k0 + tx] = f2h_bits(tile[tx][ty + i]);
    }
}

__global__ void wsplit_kernel(const float* __restrict__ W,
                              unsigned short* __restrict__ Wh,
                              int Kd, int Nd)
{
    wsplit_body(W, Wh, Kd, Nd);
}

__global__ void wsplit2_kernel(const float* __restrict__ Wa,
                               unsigned short* __restrict__ Wha,
                               const float* __restrict__ Wb,
                               unsigned short* __restrict__ Whb,
                               int Kd, int Nd)
{
    if (blockIdx.z == 0) wsplit_body(Wa, Wha, Kd, Nd);
    else                 wsplit_body(Wb, Whb, Kd, Nd);
}

// fp32 -> fp16 elementwise
__global__ void h_convert_kernel(const float* __restrict__ X,
                                 unsigned short* __restrict__ Xh, int n)
{
    int idx = blockIdx.x * blockDim.x + threadIdx.x;
    if (idx < n) Xh[idx] = f2h_bits(X[idx]);
}

// ---------------------------------------------------------------------------
// Geo embedding + 3-layer 64-wide MLP (fused) -> fp16 output
// ---------------------------------------------------------------------------
__global__ __launch_bounds__(128)
void geo_kernel(const float* __restrict__ prop,
                const float* __restrict__ w1, const float* __restrict__ b1,
                const float* __restrict__ w2, const float* __restrict__ b2,
                const float* __restrict__ w3, const float* __restrict__ b3,
                unsigned short* __restrict__ G3)
{
    __shared__ float sw1[GEO * GEO], sw2[GEO * GEO], sw3[GEO * GEO];
    __shared__ float sb1[GEO], sb2[GEO], sb3[GEO];
    __shared__ float esm[128 * 65];

    const int tid = threadIdx.x;
    for (int t = tid; t < GEO * GEO; t += blockDim.x) {
        sw1[t] = w1[t]; sw2[t] = w2[t]; sw3[t] = w3[t];
    }
    for (int t = tid; t < GEO; t += blockDim.x) {
        sb1[t] = b1[t]; sb2[t] = b2[t]; sb3[t] = b3[t];
    }
    __syncthreads();

    const int row = blockIdx.x * blockDim.x + tid;
    const int b = row >> 14;
    const int i = (row >> 7) & (NP - 1);
    const int j = row & (NP - 1);

    const float* pi = prop + ((size_t)(b * NP + i)) * 4;
    const float* pj = prop + ((size_t)(b * NP + j)) * 4;
    float wi = pi[2] - pi[0] + 1.f, hi = pi[3] - pi[1] + 1.f;
    float wj = pj[2] - pj[0] + 1.f, hj = pj[3] - pj[1] + 1.f;
    float cxi = 0.5f * (pi[0] + pi[2]), cyi = 0.5f * (pi[1] + pi[3]);
    float cxj = 0.5f * (pj[0] + pj[2]), cyj = 0.5f * (pj[1] + pj[3]);

    float pos[4];
    pos[0] = (cxi - cxj) / wj;
    pos[1] = (cyi - cyj) / hj;
    pos[2] = wi / wj;
    pos[3] = hi / hj;

    const float dm[8] = {1.0f, 2.3713737f, 5.6234133f, 13.335215f,
                         31.622777f, 74.989421f, 177.82794f, 421.69650f};

    float* my = &esm[tid * 65];
#pragma unroll
    for (int p = 0; p < 4; p++) {
        float lp = logf(fmaxf(fabsf(pos[p]), 1e-3f)) * 100.f;
#pragma unroll
        for (int r = 0; r < 8; r++) {
            float arg = lp / dm[r];
            float s, cc;
            sincosf(arg, &s, &cc);
            my[p * 16 + r] = s;
            my[p * 16 + 8 + r] = cc;
        }
    }

    float acc[GEO];
#pragma unroll
    for (int o = 0; o < GEO; o++) acc[o] = sb1[o];
    for (int k = 0; k < GEO; k++) {
        float ek = my[k];
        const float* wr = &sw1[k * GEO];
#pragma unroll
        for (int o = 0; o < GEO; o++) acc[o] = fmaf(ek, wr[o], acc[o]);
    }
#pragma unroll
    for (int o = 0; o < GEO; o++) my[o] = fmaxf(acc[o], 0.f);

#pragma unroll
    for (int o = 0; o < GEO; o++) acc[o] = sb2[o];
    for (int k = 0; k < GEO; k++) {
        float ek = my[k];
        const float* wr = &sw2[k * GEO];
#pragma unroll
        for (int o = 0; o < GEO; o++) acc[o] = fmaf(ek, wr[o], acc[o]);
    }
#pragma unroll
    for (int o = 0; o < GEO; o++) my[o] = fmaxf(acc[o], 0.f);

#pragma unroll
    for (int o = 0; o < GEO; o++) acc[o] = sb3[o];
    for (int k = 0; k < GEO; k++) {
        float ek = my[k];
        const float* wr = &sw3[k * GEO];
#pragma unroll
        for (int o = 0; o < GEO; o++) acc[o] = fmaf(ek, wr[o], acc[o]);
    }
    unsigned short* outp = G3 + (size_t)row * GEO;
#pragma unroll
    for (int o = 0; o < GEO; o++) outp[o] = f2h_bits(acc[o]);
}

// ---------------------------------------------------------------------------
// heads
// ---------------------------------------------------------------------------
__global__ __launch_bounds__(128)
void heads_kernel(const float* __restrict__ X,
                  const float* __restrict__ subject,
                  const float* __restrict__ obj,
                  const float* __restrict__ cs_w, const float* __restrict__ cs_b,
                  const float* __restrict__ cso_w, const float* __restrict__ cso_b,
                  float* __restrict__ out)
{
    int row = blockIdx.x;
    int b = row >> 7;
    int tid = threadIdx.x;

    float as = 0.f, ao = 0.f;
    for (int k = tid; k < DIM; k += 128) {
        float xv = X[(size_t)row * DIM + k];
        float sv = subject[(size_t)b * DIM + k];
        float ov = obj[(size_t)b * DIM + k];
        as += xv * cs_w[k] + sv * cs_w[DIM + k];
        ao += xv * cso_w[k] + ov * cso_w[DIM + k];
    }
    __shared__ float rs[128], ro[128];
    rs[tid] = as; ro[tid] = ao;
    __syncthreads();
    for (int s = 64; s > 0; s >>= 1) {
        if (tid < s) { rs[tid] += rs[tid + s]; ro[tid] += ro[tid + s]; }
        __syncthreads();
    }
    if (tid == 0) {
        float s1 = rs[0] + cs_b[0];
        float s2 = ro[0] + cso_b[0];
        out[row * 2 + 0] = 1.f / (1.f + expf(-s1));
        out[row * 2 + 1] = 1.f / (1.f + expf(-s2));
    }
}

// ---------------------------------------------------------------------------
// Launch (R16 + fp16 FA/FB + l2/l3 mtile-half pipelining)
// ---------------------------------------------------------------------------
extern "C" void kernel_launch(void* const* d_in, const int* in_sizes, int n_in,
                              void* d_out, int out_size)
{
    const float* feats   = (const float*)d_in[0];
    const float* subject = (const float*)d_in[1];
    const float* obj     = (const float*)d_in[2];
    const float* prop    = (const float*)d_in[3];
    const float* gp_w1 = (const float*)d_in[4];
    const float* gp_b1 = (const float*)d_in[5];
    const float* gp_w2 = (const float*)d_in[6];
    const float* gp_b2 = (const float*)d_in[7];
    const float* gp_w3 = (const float*)d_in[8];
    const float* gp_b3 = (const float*)d_in[9];
    const float* pm_w1 = (const float*)d_in[10];
    const float* pm_b1 = (const float*)d_in[11];
    const float* pm_w2 = (const float*)d_in[12];
    const float* pm_b2 = (const float*)d_in[13];
    const float* pm_w3 = (const float*)d_in[14];
    const float* pm_b3 = (const float*)d_in[15];
    const float* ag_w1 = (const float*)d_in[16];
    const float* ag_b1 = (const float*)d_in[17];
    const float* ag_w2 = (const float*)d_in[18];
    const float* ag_b2 = (const float*)d_in[19];
    const float* ag_w3 = (const float*)d_in[20];
    const float* ag_b3 = (const float*)d_in[21];
    const float* cs_w  = (const float*)d_in[22];
    const float* cs_b  = (const float*)d_in[23];
    const float* cso_w = (const float*)d_in[24];
    const float* cso_b = (const float*)d_in[25];
    float* out = (float*)d_out;

    float *SA, *P;
    unsigned short *FAh, *FBh, *featsH, *TH, *SAh, *SBh;
    unsigned short *G3, *H1, *H2, *W1, *W2, *W3, *WFA, *WFB, *AG1, *AG2, *AG3;
    cudaGetSymbolAddress((void**)&SA, g_SA);
    cudaGetSymbolAddress((void**)&P,  g_P);
    cudaGetSymbolAddress((void**)&FAh, g_FAh);
    cudaGetSymbolAddress((void**)&FBh, g_FBh);
    cudaGetSymbolAddress((void**)&featsH, g_featsH);
    cudaGetSymbolAddress((void**)&TH, g_TH);
    cudaGetSymbolAddress((void**)&SAh, g_SAh);
    cudaGetSymbolAddress((void**)&SBh, g_SBh);
    cudaGetSymbolAddress((void**)&G3, g_G3);
    cudaGetSymbolAddress((void**)&H1, g_H1);
    cudaGetSymbolAddress((void**)&H2, g_H2);
    cudaGetSymbolAddress((void**)&W1, g_W1);
    cudaGetSymbolAddress((void**)&W2, g_W2);
    cudaGetSymbolAddress((void**)&W3, g_W3);
    cudaGetSymbolAddress((void**)&WFA, g_WFA);
    cudaGetSymbolAddress((void**)&WFB, g_WFB);
    cudaGetSymbolAddress((void**)&AG1, g_AG1);
    cudaGetSymbolAddress((void**)&AG2, g_AG2);
    cudaGetSymbolAddress((void**)&AG3, g_AG3);

    cudaFuncSetAttribute(hmma_l2_kernel,
                         cudaFuncAttributeMaxDynamicSharedMemorySize, HMMA_SMEM);
    cudaFuncSetAttribute(hmma_l3_topk_kernel,
                         cudaFuncAttributeMaxDynamicSharedMemorySize, HMMA_SMEM);
    cudaFuncSetAttribute(hmma_l1_kernel,
                         cudaFuncAttributeMaxDynamicSharedMemorySize, L1_SMEM);
    cudaFuncSetAttribute(hmma_sk_kernel,
                         cudaFuncAttributeMaxDynamicSharedMemorySize, L1_SMEM);

    dim3 ghm(DIM / 128, MBIG / 128);          // (8, 256)
    dim3 ghm_h(DIM / 128, MBIG / 256);        // (8, 128) half
    dim3 gws(DIM / 32, DIM / 32);
    dim3 gws2(DIM / 32, DIM / 32, 2);
    dim3 gws1(DIM / 32, GEO / 32);
    const int MN = MN_SMALL;
    const int HALF_MT = MBIG / 256;           // 128

    // ---- forked prologue ----
    cudaStream_t s1;
    cudaEvent_t eFork, eJoin, eJoin2, eJoin3, eL2a, eL3a;
    bool forked =
        (cudaStreamCreateWithFlags(&s1, cudaStreamNonBlocking) == cudaSuccess) &&
        (cudaEventCreateWithFlags(&eFork, cudaEventDisableTiming) == cudaSuccess) &&
        (cudaEventCreateWithFlags(&eJoin, cudaEventDisableTiming) == cudaSuccess) &&
        (cudaEventCreateWithFlags(&eJoin2, cudaEventDisableTiming) == cudaSuccess) &&
        (cudaEventCreateWithFlags(&eJoin3, cudaEventDisableTiming) == cudaSuccess) &&
        (cudaEventCreateWithFlags(&eL2a, cudaEventDisableTiming) == cudaSuccess) &&
        (cudaEventCreateWithFlags(&eL3a, cudaEventDisableTiming) == cudaSuccess);

    if (forked) forked = (cudaEventRecord(eFork, 0) == cudaSuccess) &&
                         (cudaStreamWaitEvent(s1, eFork, 0) == cudaSuccess);

    cudaStream_t sb = forked ? s1 : 0;

    // branch B: geo first (l1 dep) -> join1; W2/W3 -> join2; AG converts -> join3
    geo_kernel<<<MBIG / 128, 128, 0, sb>>>(prop, gp_w1, gp_b1, gp_w2, gp_b2,
                                           gp_w3, gp_b3, G3);
    if (forked) cudaEventRecord(eJoin, s1);
    wsplit2_kernel<<<gws2, dim3(32, 8), 0, sb>>>(pm_w2, W2, pm_w3, W3,
                                                 DIM, DIM);
    if (forked) cudaEventRecord(eJoin2, s1);
    wsplit_kernel<<<dim3(DIM / 32, 2 * DIM / 32), dim3(32, 8), 0, sb>>>(
        ag_w1, AG1, 2 * DIM, DIM);
    wsplit2_kernel<<<gws2, dim3(32, 8), 0, sb>>>(ag_w2, AG2, ag_w3, AG3,
                                                 DIM, DIM);
    if (forked) cudaEventRecord(eJoin3, s1);

    // main branch: converts + FA/FB split-K HMMA (fp16 outputs)
    h_convert_kernel<<<MN / 256, 256>>>(feats, featsH, MN);
    wsplit_kernel<<<gws1, dim3(32, 8)>>>(pm_w1 + (size_t)2 * DIM * DIM,
                                         W1, GEO, DIM);
    wsplit2_kernel<<<gws2, dim3(32, 8)>>>(pm_w1, WFA,
                                          pm_w1 + (size_t)DIM * DIM, WFB,
                                          DIM, DIM);
    dim3 gsk32(DIM / 128, MSMALL / 128, 32);   // (8, 2, 32)
    hmma_sk_kernel<<<gsk32, 256, L1_SMEM>>>(featsH, nullptr, WFA, WFB,
                                            P, DIM, 16, 1);
    skreduce_dual_h<<<(2 * MN) / 256, 256>>>(P, 16, FAh, FBh, MN);

    if (forked) cudaStreamWaitEvent(0, eJoin, 0);

    // Pairwise layer 1 (fp16 HMMA, K=64) -> H1 fp16
    hmma_l1_kernel<<<ghm, 256, L1_SMEM>>>(G3, W1, pm_b1, FAh, FBh, H1);

    if (forked) cudaStreamWaitEvent(0, eJoin2, 0);

    if (forked) {
        // mtile-half pipelining: main: l2a -> l2b -> l3b ; side: l3a after l2a
        hmma_l2_kernel<<<ghm_h, 256, HMMA_SMEM>>>(H1, W2, pm_b2, H2, 0);
        cudaEventRecord(eL2a, 0);
        hmma_l2_kernel<<<ghm_h, 256, HMMA_SMEM>>>(H1, W2, pm_b2, H2, HALF_MT);
        cudaStreamWaitEvent(s1, eL2a, 0);
        hmma_l3_topk_kernel<<<ghm_h, 256, HMMA_SMEM, s1>>>(H2, W3, pm_b3, TH, 0);
        cudaEventRecord(eL3a, s1);
        hmma_l3_topk_kernel<<<ghm_h, 256, HMMA_SMEM>>>(H2, W3, pm_b3, TH,
                                                       HALF_MT);
        cudaStreamWaitEvent(0, eL3a, 0);
    } else {
        hmma_l2_kernel<<<ghm, 256, HMMA_SMEM>>>(H1, W2, pm_b2, H2, 0);
        hmma_l3_topk_kernel<<<ghm, 256, HMMA_SMEM>>>(H2, W3, pm_b3, TH, 0);
    }

    if (forked) cudaStreamWaitEvent(0, eJoin3, 0);

    // Aggregate MLP via HMMA split-K; ag1 = [featsH | TH] @ AG1 (dual-A)
    dim3 gsk16(DIM / 128, MSMALL / 128, 16);
    hmma_sk_kernel<<<gsk32, 256, L1_SMEM>>>(featsH, TH, AG1, nullptr,
                                            P, 2 * DIM, 16, 2);
    skreduce_h<<<MN / 256, 256>>>(P, 32, ag_b1, 1, SAh, MN, DIM);
    hmma_sk_kernel<<<gsk16, 256, L1_SMEM>>>(SAh, nullptr, AG2, nullptr,
                                            P, DIM, 16, 0);
    skreduce_h<<<MN / 256, 256>>>(P, 16, ag_b2, 1, SBh, MN, DIM);
    hmma_sk_kernel<<<gsk16, 256, L1_SMEM>>>(SBh, nullptr, AG3, nullptr,
                                            P, DIM, 16, 0);
    skreduce<<<MN / 256, 256>>>(P, 16, ag_b3, 0, SA, MN, DIM);

    // Heads
    heads_kernel<<<MSMALL, 128>>>(SA, subject, obj, cs_w, cs_b, cso_w, cso_b, out);
}